// round 9
// baseline (speedup 1.0000x reference)
#include <cuda_runtime.h>

// ---------------------------------------------------------------------------
// SwinIR-lite forward: conv3x3(3->60) -> 36 x [LN+WindowAttn+res, LN+MLP+res]
// -> conv3x3(60->12) + PixelShuffle(2).  All fp32.  B=2, H=W=128, C=60.
// R9: GEMMs TM=64 (MRep=2 M-tiles/thread, grid 512), all-thread staging,
//     bank-conflict-free xs (stride 68), looser reg caps. Attention = R2 form.
// ---------------------------------------------------------------------------

constexpr int Bn   = 2;
constexpr int Hc   = 128;
constexpr int Wc   = 128;
constexpr int Cch  = 60;
constexpr int NHEADS = 3;
constexpr int NTOK = Bn * Hc * Wc;          // 32768 tokens
constexpr int QKVC = 180;
constexpr int FCC  = 120;
constexpr int NL   = 36;

// Scratch (device globals; no allocation allowed)
__device__ float g_feat[NTOK * Cch];        // 7.5 MB
__device__ float g_qkv [NTOK * QKVC];       // 22.5 MB
__device__ float g_attn[NTOK * Cch];        // 7.5 MB
__device__ float g_mlp [NTOK * FCC];        // 15 MB

// ---------------------------------------------------------------------------
// conv3x3 3->60, NCHW in -> NHWC (token-major) out
// ---------------------------------------------------------------------------
__global__ __launch_bounds__(256) void conv_in_k(
    const float* __restrict__ x, const float* __restrict__ w,
    const float* __restrict__ b)
{
    int idx = blockIdx.x * blockDim.x + threadIdx.x;
    if (idx >= NTOK * Cch) return;
    int co = idx % Cch;
    int p  = idx / Cch;
    int wx = p % Wc;
    int hy = (p / Wc) % Hc;
    int bb = p / (Wc * Hc);
    float acc = b[co];
#pragma unroll
    for (int ci = 0; ci < 3; ci++) {
#pragma unroll
        for (int kh = 0; kh < 3; kh++) {
            int hh = hy + kh - 1;
            if ((unsigned)hh >= (unsigned)Hc) continue;
#pragma unroll
            for (int kw = 0; kw < 3; kw++) {
                int ww2 = wx + kw - 1;
                if ((unsigned)ww2 >= (unsigned)Wc) continue;
                acc += x[((bb * 3 + ci) * Hc + hh) * Wc + ww2] *
                       w[((co * 3 + ci) * 3 + kh) * 3 + kw];
            }
        }
    }
    g_feat[idx] = acc;
}

// ---------------------------------------------------------------------------
// GEMM core: thread computes MRep tiles of 4M x 4N.
//   per k: 1 LDS.128 (w) + MRep LDS.128 (x) -> MRep*16 FFMA.
// Thread map: t = ng*MG + mg; n0 = ng*4, m0 = mg*4 (+ r*4*MG per tile).
// TM = 4*MG*MRep.  xs row stride XST = TM+4 (bank spread, 16B aligned).
// ---------------------------------------------------------------------------

// LN (over K) + GEMM [T,K]@[K,N] + bias (+ optional Swish) -> out.
template <int K, int N, int MG, int MRep, bool SWISH, bool OUT_MLP, int NTHR, int MINB>
__global__ __launch_bounds__(NTHR, MINB) void ln_gemm_k(
    const float* __restrict__ gamma, const float* __restrict__ beta,
    const float* __restrict__ w, const float* __restrict__ bias)
{
    constexpr int TM  = 4 * MG * MRep;
    constexpr int XST = TM + 4;
    extern __shared__ float sm[];
    float* ws = sm;                  // K*N
    float* bs = sm + K * N;          // N
    float* gs = bs + N;              // K (gamma)
    float* bt = gs + K;              // K (beta)
    float* xs = bt + K;              // K*XST (k-major)
    const int tid = threadIdx.x;
    const int T0  = blockIdx.x * TM;

    {   // cooperative weight load (float4)
        const float4* wg = (const float4*)w;
        float4*       w4 = (float4*)ws;
        for (int i = tid; i < K * N / 4; i += NTHR) w4[i] = wg[i];
    }
    for (int i = tid; i < N; i += NTHR)  bs[i] = bias[i];
    for (int i = tid; i < K; i += NTHR) { gs[i] = gamma[i]; bt[i] = beta[i]; }
    __syncthreads();

    if (tid < TM) {
        const float4* row = (const float4*)(g_feat + (size_t)(T0 + tid) * K);
        float s = 0.f, s2 = 0.f;
#pragma unroll
        for (int i = 0; i < K / 4; i++) {
            float4 v = row[i];
            s  += v.x + v.y + v.z + v.w;
            s2 += v.x * v.x + v.y * v.y + v.z * v.z + v.w * v.w;
            xs[(4 * i + 0) * XST + tid] = v.x;
            xs[(4 * i + 1) * XST + tid] = v.y;
            xs[(4 * i + 2) * XST + tid] = v.z;
            xs[(4 * i + 3) * XST + tid] = v.w;
        }
        float mu  = s * (1.0f / K);
        float var = s2 * (1.0f / K) - mu * mu;
        float rs  = rsqrtf(var + 1e-5f);
#pragma unroll
        for (int k = 0; k < K; k++)
            xs[k * XST + tid] = (xs[k * XST + tid] - mu) * rs * gs[k] + bt[k];
    }
    __syncthreads();

    constexpr int USED = (N / 4) * MG;
    if (tid < USED) {
        const int ng = tid / MG, mg = tid % MG;
        const int n0 = ng * 4,   m0 = mg * 4;
        float4 bv = *(const float4*)(bs + n0);
        float4 acc[MRep][4];
#pragma unroll
        for (int r = 0; r < MRep; r++)
#pragma unroll
            for (int j = 0; j < 4; j++) acc[r][j] = bv;
#pragma unroll
        for (int k = 0; k < K; k++) {
            float4 wv = *(const float4*)(ws + k * N + n0);
#pragma unroll
            for (int r = 0; r < MRep; r++) {
                float4 xv = *(const float4*)(xs + k * XST + m0 + r * 4 * MG);
                acc[r][0].x = fmaf(xv.x, wv.x, acc[r][0].x);
                acc[r][0].y = fmaf(xv.x, wv.y, acc[r][0].y);
                acc[r][0].z = fmaf(xv.x, wv.z, acc[r][0].z);
                acc[r][0].w = fmaf(xv.x, wv.w, acc[r][0].w);
                acc[r][1].x = fmaf(xv.y, wv.x, acc[r][1].x);
                acc[r][1].y = fmaf(xv.y, wv.y, acc[r][1].y);
                acc[r][1].z = fmaf(xv.y, wv.z, acc[r][1].z);
                acc[r][1].w = fmaf(xv.y, wv.w, acc[r][1].w);
                acc[r][2].x = fmaf(xv.z, wv.x, acc[r][2].x);
                acc[r][2].y = fmaf(xv.z, wv.y, acc[r][2].y);
                acc[r][2].z = fmaf(xv.z, wv.z, acc[r][2].z);
                acc[r][2].w = fmaf(xv.z, wv.w, acc[r][2].w);
                acc[r][3].x = fmaf(xv.w, wv.x, acc[r][3].x);
                acc[r][3].y = fmaf(xv.w, wv.y, acc[r][3].y);
                acc[r][3].z = fmaf(xv.w, wv.z, acc[r][3].z);
                acc[r][3].w = fmaf(xv.w, wv.w, acc[r][3].w);
            }
        }
        float* out = OUT_MLP ? g_mlp : g_qkv;
#pragma unroll
        for (int r = 0; r < MRep; r++) {
#pragma unroll
            for (int j = 0; j < 4; j++) {
                float4 a = acc[r][j];
                if (SWISH) {
                    a.x /= 1.f + __expf(-a.x); a.y /= 1.f + __expf(-a.y);
                    a.z /= 1.f + __expf(-a.z); a.w /= 1.f + __expf(-a.w);
                }
                size_t ob = (size_t)(T0 + m0 + r * 4 * MG + j) * N + n0;
                *(float4*)(out + ob) = a;
            }
        }
    }
}

// GEMM [T,K]@[K,N] + bias + residual-add into g_feat.
template <int K, int N, int MG, int MRep, bool IN_MLP, int NTHR, int MINB>
__global__ __launch_bounds__(NTHR, MINB) void gemm_resid_k(
    const float* __restrict__ w, const float* __restrict__ bias)
{
    constexpr int TM  = 4 * MG * MRep;
    constexpr int XST = TM + 4;
    extern __shared__ float sm[];
    float* ws = sm;
    float* bs = sm + K * N;
    float* xs = bs + N;
    const int tid = threadIdx.x;
    const int T0  = blockIdx.x * TM;
    const float* in = IN_MLP ? g_mlp : g_attn;

    {
        const float4* wg = (const float4*)w;
        float4*       w4 = (float4*)ws;
        for (int i = tid; i < K * N / 4; i += NTHR) w4[i] = wg[i];
    }
    for (int i = tid; i < N; i += NTHR) bs[i] = bias[i];

    {   // all-thread k-major staging of x tile
        constexpr int KT4 = K / 4;
        for (int i = tid; i < TM * KT4; i += NTHR) {
            int row = i / KT4, c4 = i % KT4;
            float4 v = *(const float4*)(in + (size_t)(T0 + row) * K + c4 * 4);
            xs[(4 * c4 + 0) * XST + row] = v.x;
            xs[(4 * c4 + 1) * XST + row] = v.y;
            xs[(4 * c4 + 2) * XST + row] = v.z;
            xs[(4 * c4 + 3) * XST + row] = v.w;
        }
    }
    __syncthreads();

    constexpr int USED = (N / 4) * MG;
    if (tid < USED) {
        const int ng = tid / MG, mg = tid % MG;
        const int n0 = ng * 4,   m0 = mg * 4;
        float4 bv = *(const float4*)(bs + n0);
        float4 acc[MRep][4];
#pragma unroll
        for (int r = 0; r < MRep; r++)
#pragma unroll
            for (int j = 0; j < 4; j++) acc[r][j] = bv;
#pragma unroll
        for (int k = 0; k < K; k++) {
            float4 wv = *(const float4*)(ws + k * N + n0);
#pragma unroll
            for (int r = 0; r < MRep; r++) {
                float4 xv = *(const float4*)(xs + k * XST + m0 + r * 4 * MG);
                acc[r][0].x = fmaf(xv.x, wv.x, acc[r][0].x);
                acc[r][0].y = fmaf(xv.x, wv.y, acc[r][0].y);
                acc[r][0].z = fmaf(xv.x, wv.z, acc[r][0].z);
                acc[r][0].w = fmaf(xv.x, wv.w, acc[r][0].w);
                acc[r][1].x = fmaf(xv.y, wv.x, acc[r][1].x);
                acc[r][1].y = fmaf(xv.y, wv.y, acc[r][1].y);
                acc[r][1].z = fmaf(xv.y, wv.z, acc[r][1].z);
                acc[r][1].w = fmaf(xv.y, wv.w, acc[r][1].w);
                acc[r][2].x = fmaf(xv.z, wv.x, acc[r][2].x);
                acc[r][2].y = fmaf(xv.z, wv.y, acc[r][2].y);
                acc[r][2].z = fmaf(xv.z, wv.z, acc[r][2].z);
                acc[r][2].w = fmaf(xv.z, wv.w, acc[r][2].w);
                acc[r][3].x = fmaf(xv.w, wv.x, acc[r][3].x);
                acc[r][3].y = fmaf(xv.w, wv.y, acc[r][3].y);
                acc[r][3].z = fmaf(xv.w, wv.z, acc[r][3].z);
                acc[r][3].w = fmaf(xv.w, wv.w, acc[r][3].w);
            }
        }
#pragma unroll
        for (int r = 0; r < MRep; r++) {
#pragma unroll
            for (int j = 0; j < 4; j++) {
                size_t ob = (size_t)(T0 + m0 + r * 4 * MG + j) * N + n0;
                float4 rr = *(const float4*)(g_feat + ob);
                rr.x += acc[r][j].x; rr.y += acc[r][j].y;
                rr.z += acc[r][j].z; rr.w += acc[r][j].w;
                *(float4*)(g_feat + ob) = rr;
            }
        }
    }
}

// ---------------------------------------------------------------------------
// Window attention (R2 form).  Block = (window, head), 256 threads = queries.
// Roll by index arithmetic; streaming softmax w/o max-subtract (logits tiny;
// masked = -100).
// ---------------------------------------------------------------------------
__global__ __launch_bounds__(256) void attn_k(int wh, int ww, int sh, int sw,
                                              int shifted)
{
    __shared__ float4 ks [256][5];
    __shared__ float4 vsm[256][5];
    __shared__ int    rg [256];

    const int n    = threadIdx.x;
    const int head = blockIdx.y;
    const int win  = blockIdx.x;
    const int nW   = Wc / ww;
    const int perB = (Hc / wh) * nW;
    const int b    = win / perB;
    const int wr_  = win % perB;
    const int wy   = wr_ / nW, wx = wr_ % nW;
    const int iy   = n / ww,   ix = n % ww;
    const int hr   = wy * wh + iy;
    const int wrr  = wx * ww + ix;
    int hs = hr + sh;   if (hs  >= Hc) hs  -= Hc;
    int wsv = wrr + sw; if (wsv >= Wc) wsv -= Wc;
    const size_t g = ((size_t)b * Hc + hs) * Wc + wsv;

    const float4* qp    = (const float4*)g_qkv;
    const size_t  base4 = g * 45 + (size_t)head * 5;   // 180 floats / token
    const float   scale = 0.223606797749979f;          // 20^-0.5

    float4 q[5];
#pragma unroll
    for (int i = 0; i < 5; i++) {
        float4 t = qp[base4 + i];
        t.x *= scale; t.y *= scale; t.z *= scale; t.w *= scale;
        q[i] = t;
        ks [n][i] = qp[base4 + 15 + i];
        vsm[n][i] = qp[base4 + 30 + i];
    }
    int myreg = 0;
    if (shifted) {
        int rh = (hr  < Hc - wh) ? 0 : ((hr  < Hc - sh) ? 1 : 2);
        int rw = (wrr < Wc - ww) ? 0 : ((wrr < Wc - sw) ? 1 : 2);
        myreg = rh * 3 + rw;
        rg[n] = myreg;
    }
    __syncthreads();

    float4 acc[5];
#pragma unroll
    for (int i = 0; i < 5; i++) acc[i] = make_float4(0.f, 0.f, 0.f, 0.f);
    float denom = 0.f;

    if (shifted) {
        for (int m = 0; m < 256; m++) {
            float s = 0.f;
#pragma unroll
            for (int i = 0; i < 5; i++) {
                float4 kv = ks[m][i];
                s = fmaf(q[i].x, kv.x, s); s = fmaf(q[i].y, kv.y, s);
                s = fmaf(q[i].z, kv.z, s); s = fmaf(q[i].w, kv.w, s);
            }
            if (rg[m] != myreg) s -= 100.f;
            float p = __expf(s);
            denom += p;
#pragma unroll
            for (int i = 0; i < 5; i++) {
                float4 vv = vsm[m][i];
                acc[i].x = fmaf(p, vv.x, acc[i].x);
                acc[i].y = fmaf(p, vv.y, acc[i].y);
                acc[i].z = fmaf(p, vv.z, acc[i].z);
                acc[i].w = fmaf(p, vv.w, acc[i].w);
            }
        }
    } else {
        for (int m = 0; m < 256; m++) {
            float s = 0.f;
#pragma unroll
            for (int i = 0; i < 5; i++) {
                float4 kv = ks[m][i];
                s = fmaf(q[i].x, kv.x, s); s = fmaf(q[i].y, kv.y, s);
                s = fmaf(q[i].z, kv.z, s); s = fmaf(q[i].w, kv.w, s);
            }
            float p = __expf(s);
            denom += p;
#pragma unroll
            for (int i = 0; i < 5; i++) {
                float4 vv = vsm[m][i];
                acc[i].x = fmaf(p, vv.x, acc[i].x);
                acc[i].y = fmaf(p, vv.y, acc[i].y);
                acc[i].z = fmaf(p, vv.z, acc[i].z);
                acc[i].w = fmaf(p, vv.w, acc[i].w);
            }
        }
    }

    float inv = 1.f / denom;
    float4* op = (float4*)g_attn;
    size_t  ob = g * 15 + (size_t)head * 5;     // 60 floats / token
#pragma unroll
    for (int i = 0; i < 5; i++) {
        float4 t = acc[i];
        t.x *= inv; t.y *= inv; t.z *= inv; t.w *= inv;
        op[ob + i] = t;
    }
}

// ---------------------------------------------------------------------------
// conv3x3 60->12 + PixelShuffle(2) fused.
// ---------------------------------------------------------------------------
__global__ __launch_bounds__(256) void conv_out_k(
    const float* __restrict__ lw, const float* __restrict__ lb,
    float* __restrict__ out)
{
    const int TOT = Bn * 3 * 256 * 256;
    int idx = blockIdx.x * blockDim.x + threadIdx.x;
    if (idx >= TOT) return;
    int w2 = idx & 255;
    int h2 = (idx >> 8) & 255;
    int c  = (idx >> 16) % 3;
    int bb = idx / (3 * 65536);
    int co = c * 4 + (h2 & 1) * 2 + (w2 & 1);
    int h  = h2 >> 1, w = w2 >> 1;
    float acc = lb[co];
#pragma unroll
    for (int kh = 0; kh < 3; kh++) {
        int hh = h + kh - 1;
        if ((unsigned)hh >= (unsigned)Hc) continue;
#pragma unroll
        for (int kw = 0; kw < 3; kw++) {
            int ww2 = w + kw - 1;
            if ((unsigned)ww2 >= (unsigned)Wc) continue;
            const float* fp = g_feat + ((size_t)(bb * Hc + hh) * Wc + ww2) * Cch;
            const float* wp = lw + co * (Cch * 9) + kh * 3 + kw;
#pragma unroll
            for (int ci = 0; ci < Cch; ci++)
                acc = fmaf(fp[ci], wp[ci * 9], acc);
        }
    }
    out[idx] = acc;
}

// ---------------------------------------------------------------------------
// Launch
// ---------------------------------------------------------------------------
extern "C" void kernel_launch(void* const* d_in, const int* in_sizes, int n_in,
                              void* d_out, int out_size)
{
    (void)in_sizes; (void)n_in; (void)out_size;
    const float* x      = (const float*)d_in[0];
    const float* conv_w = (const float*)d_in[1];
    const float* conv_b = (const float*)d_in[2];
    const float* ln1_g  = (const float*)d_in[3];
    const float* ln1_b  = (const float*)d_in[4];
    const float* qkv_w  = (const float*)d_in[5];
    const float* qkv_b  = (const float*)d_in[6];
    const float* proj_w = (const float*)d_in[7];
    const float* proj_b = (const float*)d_in[8];
    const float* ln2_g  = (const float*)d_in[9];
    const float* ln2_b  = (const float*)d_in[10];
    const float* fc1_w  = (const float*)d_in[11];
    const float* fc1_b  = (const float*)d_in[12];
    const float* fc2_w  = (const float*)d_in[13];
    const float* fc2_b  = (const float*)d_in[14];
    const float* last_w = (const float*)d_in[15];
    const float* last_b = (const float*)d_in[16];
    float* out = (float*)d_out;

    // All GEMMs: MG=8, MRep=2 -> TM=64, grid 512.  XST=68.
    // smem (floats): ws K*N + bs N (+ gs/bt K each for LN) + xs K*68
    constexpr int SM_QKV  = (60 * 180 + 180 + 120 + 60 * 68)  * 4;  // 60720
    constexpr int SM_FC1  = (60 * 120 + 120 + 120 + 60 * 68)  * 4;  // 46080
    constexpr int SM_PROJ = (60 * 60  + 60  + 60 * 68)  * 4;        // 30960
    constexpr int SM_FC2  = (120 * 60 + 60  + 120 * 68) * 4;        // 61680

    cudaFuncSetAttribute(ln_gemm_k<60, 180, 8, 2, false, false, 384, 2>,
                         cudaFuncAttributeMaxDynamicSharedMemorySize, SM_QKV);
    cudaFuncSetAttribute(ln_gemm_k<60, 120, 8, 2, true, true, 256, 3>,
                         cudaFuncAttributeMaxDynamicSharedMemorySize, SM_FC1);
    cudaFuncSetAttribute(gemm_resid_k<60, 60, 8, 2, false, 128, 4>,
                         cudaFuncAttributeMaxDynamicSharedMemorySize, SM_PROJ);
    cudaFuncSetAttribute(gemm_resid_k<120, 60, 8, 2, true, 128, 3>,
                         cudaFuncAttributeMaxDynamicSharedMemorySize, SM_FC2);

    conv_in_k<<<(NTOK * Cch + 255) / 256, 256>>>(x, conv_w, conv_b);

    for (int l = 0; l < NL; l++) {
        int i  = l % 6;
        int wi = i % 2;
        int wh = wi ? 8 : 32;
        int ww = wi ? 32 : 8;
        int shifted = (i % 4) >= 2;
        int sh = shifted ? (wi ? 4 : 16) : 0;
        int sw = shifted ? (wi ? 16 : 4) : 0;

        ln_gemm_k<60, 180, 8, 2, false, false, 384, 2>
            <<<NTOK / 64, 384, SM_QKV>>>(ln1_g + l * 60, ln1_b + l * 60,
                                         qkv_w + (size_t)l * 60 * 180,
                                         qkv_b + l * 180);

        attn_k<<<dim3(Bn * 64, NHEADS), 256>>>(wh, ww, sh, sw, shifted);

        gemm_resid_k<60, 60, 8, 2, false, 128, 4>
            <<<NTOK / 64, 128, SM_PROJ>>>(proj_w + (size_t)l * 3600,
                                          proj_b + l * 60);

        ln_gemm_k<60, 120, 8, 2, true, true, 256, 3>
            <<<NTOK / 64, 256, SM_FC1>>>(ln2_g + l * 60, ln2_b + l * 60,
                                         fc1_w + (size_t)l * 7200,
                                         fc1_b + l * 120);

        gemm_resid_k<120, 60, 8, 2, true, 128, 3>
            <<<NTOK / 64, 128, SM_FC2>>>(fc2_w + (size_t)l * 7200,
                                         fc2_b + l * 60);
    }

    conv_out_k<<<(Bn * 3 * 256 * 256 + 255) / 256, 256>>>(last_w, last_b, out);
}

// round 10
// speedup vs baseline: 1.0905x; 1.0905x over previous
#include <cuda_runtime.h>

// ---------------------------------------------------------------------------
// SwinIR-lite forward: conv3x3(3->60) -> 36 x [LN+WindowAttn+res, LN+MLP+res]
// -> conv3x3(60->12) + PixelShuffle(2).  All fp32.  B=2, H=W=128, C=60.
// R10: R8 geometry (TM=32, grid 1024, 4Mx4N tiles) + all-thread staging,
//      padded k-major xs (XST=36, bank spread), 3-phase parallel LN.
// ---------------------------------------------------------------------------

constexpr int Bn   = 2;
constexpr int Hc   = 128;
constexpr int Wc   = 128;
constexpr int Cch  = 60;
constexpr int NHEADS = 3;
constexpr int NTOK = Bn * Hc * Wc;          // 32768 tokens
constexpr int QKVC = 180;
constexpr int FCC  = 120;
constexpr int NL   = 36;

// Scratch (device globals; no allocation allowed)
__device__ float g_feat[NTOK * Cch];        // 7.5 MB
__device__ float g_qkv [NTOK * QKVC];       // 22.5 MB
__device__ float g_attn[NTOK * Cch];        // 7.5 MB
__device__ float g_mlp [NTOK * FCC];        // 15 MB

// ---------------------------------------------------------------------------
// conv3x3 3->60, NCHW in -> NHWC (token-major) out
// ---------------------------------------------------------------------------
__global__ __launch_bounds__(256) void conv_in_k(
    const float* __restrict__ x, const float* __restrict__ w,
    const float* __restrict__ b)
{
    int idx = blockIdx.x * blockDim.x + threadIdx.x;
    if (idx >= NTOK * Cch) return;
    int co = idx % Cch;
    int p  = idx / Cch;
    int wx = p % Wc;
    int hy = (p / Wc) % Hc;
    int bb = p / (Wc * Hc);
    float acc = b[co];
#pragma unroll
    for (int ci = 0; ci < 3; ci++) {
#pragma unroll
        for (int kh = 0; kh < 3; kh++) {
            int hh = hy + kh - 1;
            if ((unsigned)hh >= (unsigned)Hc) continue;
#pragma unroll
            for (int kw = 0; kw < 3; kw++) {
                int ww2 = wx + kw - 1;
                if ((unsigned)ww2 >= (unsigned)Wc) continue;
                acc += x[((bb * 3 + ci) * Hc + hh) * Wc + ww2] *
                       w[((co * 3 + ci) * 3 + kh) * 3 + kw];
            }
        }
    }
    g_feat[idx] = acc;
}

// ---------------------------------------------------------------------------
// GEMM core: each thread computes a 4M x 4N register tile.
//   per k: 1 LDS.128 (x) + 1 LDS.128 (w) -> 16 FFMA.
// Thread map: t = ng*MG + mg; n0 = ng*4, m0 = mg*4.  TM = 4*MG.  XST = TM+4.
// ---------------------------------------------------------------------------

// all-thread k-major staging of a TM x K tile (float4 loads, padded scatter)
template <int K, int TM, int XST, int NTHR>
__device__ __forceinline__ void stage_x(const float* __restrict__ in,
                                        float* __restrict__ xs,
                                        int T0, int tid)
{
    constexpr int KT4 = K / 4;
    for (int i = tid; i < TM * KT4; i += NTHR) {
        int row = i / KT4, c4 = i % KT4;
        float4 v = *(const float4*)(in + (size_t)(T0 + row) * K + c4 * 4);
        xs[(4 * c4 + 0) * XST + row] = v.x;
        xs[(4 * c4 + 1) * XST + row] = v.y;
        xs[(4 * c4 + 2) * XST + row] = v.z;
        xs[(4 * c4 + 3) * XST + row] = v.w;
    }
}

// LN (over K) + GEMM [T,K]@[K,N] + bias (+ optional Swish) -> out.
template <int K, int N, int MG, bool SWISH, bool OUT_MLP, int NTHR, int MINB>
__global__ __launch_bounds__(NTHR, MINB) void ln_gemm_k(
    const float* __restrict__ gamma, const float* __restrict__ beta,
    const float* __restrict__ w, const float* __restrict__ bias)
{
    constexpr int TM  = 4 * MG;
    constexpr int XST = TM + 4;
    extern __shared__ float sm[];
    float* ws = sm;                  // K*N
    float* bs = sm + K * N;          // N
    float* gs = bs + N;              // K (gamma)
    float* bt = gs + K;              // K (beta)
    float* mu_s = bt + K;            // TM
    float* rs_s = mu_s + TM;         // TM
    float* xs = rs_s + TM;           // K*XST (k-major, padded)
    const int tid = threadIdx.x;
    const int T0  = blockIdx.x * TM;

    {   // cooperative weight load (float4)
        const float4* wg = (const float4*)w;
        float4*       w4 = (float4*)ws;
        for (int i = tid; i < K * N / 4; i += NTHR) w4[i] = wg[i];
    }
    for (int i = tid; i < N; i += NTHR)  bs[i] = bias[i];
    for (int i = tid; i < K; i += NTHR) { gs[i] = gamma[i]; bt[i] = beta[i]; }
    stage_x<K, TM, XST, NTHR>(g_feat, xs, T0, tid);
    __syncthreads();

    if (tid < TM) {   // stats from smem column (conflict-free across tid)
        float s = 0.f, s2 = 0.f;
#pragma unroll
        for (int k = 0; k < K; k++) {
            float v = xs[k * XST + tid];
            s += v; s2 += v * v;
        }
        float mu  = s * (1.0f / K);
        float var = s2 * (1.0f / K) - mu * mu;
        mu_s[tid] = mu;
        rs_s[tid] = rsqrtf(var + 1e-5f);
    }
    __syncthreads();

    // all-thread normalize in place
    for (int i = tid; i < K * TM; i += NTHR) {
        int k = i / TM, row = i % TM;
        float v = xs[k * XST + row];
        xs[k * XST + row] = (v - mu_s[row]) * rs_s[row] * gs[k] + bt[k];
    }
    __syncthreads();

    constexpr int USED = (N / 4) * MG;
    if (tid < USED) {
        const int ng = tid / MG, mg = tid % MG;
        const int n0 = ng * 4,   m0 = mg * 4;
        float4 bv = *(const float4*)(bs + n0);
        float4 a0 = bv, a1 = bv, a2 = bv, a3 = bv;   // rows m0..m0+3
#pragma unroll
        for (int k = 0; k < K; k++) {
            float4 xv = *(const float4*)(xs + k * XST + m0);
            float4 wv = *(const float4*)(ws + k * N + n0);
            a0.x = fmaf(xv.x, wv.x, a0.x); a0.y = fmaf(xv.x, wv.y, a0.y);
            a0.z = fmaf(xv.x, wv.z, a0.z); a0.w = fmaf(xv.x, wv.w, a0.w);
            a1.x = fmaf(xv.y, wv.x, a1.x); a1.y = fmaf(xv.y, wv.y, a1.y);
            a1.z = fmaf(xv.y, wv.z, a1.z); a1.w = fmaf(xv.y, wv.w, a1.w);
            a2.x = fmaf(xv.z, wv.x, a2.x); a2.y = fmaf(xv.z, wv.y, a2.y);
            a2.z = fmaf(xv.z, wv.z, a2.z); a2.w = fmaf(xv.z, wv.w, a2.w);
            a3.x = fmaf(xv.w, wv.x, a3.x); a3.y = fmaf(xv.w, wv.y, a3.y);
            a3.z = fmaf(xv.w, wv.z, a3.z); a3.w = fmaf(xv.w, wv.w, a3.w);
        }
        if (SWISH) {
            a0.x /= 1.f + __expf(-a0.x); a0.y /= 1.f + __expf(-a0.y);
            a0.z /= 1.f + __expf(-a0.z); a0.w /= 1.f + __expf(-a0.w);
            a1.x /= 1.f + __expf(-a1.x); a1.y /= 1.f + __expf(-a1.y);
            a1.z /= 1.f + __expf(-a1.z); a1.w /= 1.f + __expf(-a1.w);
            a2.x /= 1.f + __expf(-a2.x); a2.y /= 1.f + __expf(-a2.y);
            a2.z /= 1.f + __expf(-a2.z); a2.w /= 1.f + __expf(-a2.w);
            a3.x /= 1.f + __expf(-a3.x); a3.y /= 1.f + __expf(-a3.y);
            a3.z /= 1.f + __expf(-a3.z); a3.w /= 1.f + __expf(-a3.w);
        }
        float* out = OUT_MLP ? g_mlp : g_qkv;
        size_t ob = (size_t)(T0 + m0) * N + n0;
        *(float4*)(out + ob)         = a0;
        *(float4*)(out + ob + N)     = a1;
        *(float4*)(out + ob + 2 * N) = a2;
        *(float4*)(out + ob + 3 * N) = a3;
    }
}

// GEMM [T,K]@[K,N] + bias + residual-add into g_feat.
template <int K, int N, int MG, bool IN_MLP, int NTHR, int MINB>
__global__ __launch_bounds__(NTHR, MINB) void gemm_resid_k(
    const float* __restrict__ w, const float* __restrict__ bias)
{
    constexpr int TM  = 4 * MG;
    constexpr int XST = TM + 4;
    extern __shared__ float sm[];
    float* ws = sm;
    float* bs = sm + K * N;
    float* xs = bs + N;
    const int tid = threadIdx.x;
    const int T0  = blockIdx.x * TM;
    const float* in = IN_MLP ? g_mlp : g_attn;

    {
        const float4* wg = (const float4*)w;
        float4*       w4 = (float4*)ws;
        for (int i = tid; i < K * N / 4; i += NTHR) w4[i] = wg[i];
    }
    for (int i = tid; i < N; i += NTHR) bs[i] = bias[i];
    stage_x<K, TM, XST, NTHR>(in, xs, T0, tid);
    __syncthreads();

    constexpr int USED = (N / 4) * MG;
    if (tid < USED) {
        const int ng = tid / MG, mg = tid % MG;
        const int n0 = ng * 4,   m0 = mg * 4;
        float4 bv = *(const float4*)(bs + n0);
        float4 a0 = bv, a1 = bv, a2 = bv, a3 = bv;
#pragma unroll
        for (int k = 0; k < K; k++) {
            float4 xv = *(const float4*)(xs + k * XST + m0);
            float4 wv = *(const float4*)(ws + k * N + n0);
            a0.x = fmaf(xv.x, wv.x, a0.x); a0.y = fmaf(xv.x, wv.y, a0.y);
            a0.z = fmaf(xv.x, wv.z, a0.z); a0.w = fmaf(xv.x, wv.w, a0.w);
            a1.x = fmaf(xv.y, wv.x, a1.x); a1.y = fmaf(xv.y, wv.y, a1.y);
            a1.z = fmaf(xv.y, wv.z, a1.z); a1.w = fmaf(xv.y, wv.w, a1.w);
            a2.x = fmaf(xv.z, wv.x, a2.x); a2.y = fmaf(xv.z, wv.y, a2.y);
            a2.z = fmaf(xv.z, wv.z, a2.z); a2.w = fmaf(xv.z, wv.w, a2.w);
            a3.x = fmaf(xv.w, wv.x, a3.x); a3.y = fmaf(xv.w, wv.y, a3.y);
            a3.z = fmaf(xv.w, wv.z, a3.z); a3.w = fmaf(xv.w, wv.w, a3.w);
        }
        size_t ob = (size_t)(T0 + m0) * N + n0;
        float4 r0 = *(const float4*)(g_feat + ob);
        float4 r1 = *(const float4*)(g_feat + ob + N);
        float4 r2 = *(const float4*)(g_feat + ob + 2 * N);
        float4 r3 = *(const float4*)(g_feat + ob + 3 * N);
        r0.x += a0.x; r0.y += a0.y; r0.z += a0.z; r0.w += a0.w;
        r1.x += a1.x; r1.y += a1.y; r1.z += a1.z; r1.w += a1.w;
        r2.x += a2.x; r2.y += a2.y; r2.z += a2.z; r2.w += a2.w;
        r3.x += a3.x; r3.y += a3.y; r3.z += a3.z; r3.w += a3.w;
        *(float4*)(g_feat + ob)         = r0;
        *(float4*)(g_feat + ob + N)     = r1;
        *(float4*)(g_feat + ob + 2 * N) = r2;
        *(float4*)(g_feat + ob + 3 * N) = r3;
    }
}

// ---------------------------------------------------------------------------
// Window attention (R2 form).  Block = (window, head), 256 threads = queries.
// Roll by index arithmetic; streaming softmax w/o max-subtract (logits tiny;
// masked = -100).
// ---------------------------------------------------------------------------
__global__ __launch_bounds__(256) void attn_k(int wh, int ww, int sh, int sw,
                                              int shifted)
{
    __shared__ float4 ks [256][5];
    __shared__ float4 vsm[256][5];
    __shared__ int    rg [256];

    const int n    = threadIdx.x;
    const int head = blockIdx.y;
    const int win  = blockIdx.x;
    const int nW   = Wc / ww;
    const int perB = (Hc / wh) * nW;
    const int b    = win / perB;
    const int wr_  = win % perB;
    const int wy   = wr_ / nW, wx = wr_ % nW;
    const int iy   = n / ww,   ix = n % ww;
    const int hr   = wy * wh + iy;
    const int wrr  = wx * ww + ix;
    int hs = hr + sh;   if (hs  >= Hc) hs  -= Hc;
    int wsv = wrr + sw; if (wsv >= Wc) wsv -= Wc;
    const size_t g = ((size_t)b * Hc + hs) * Wc + wsv;

    const float4* qp    = (const float4*)g_qkv;
    const size_t  base4 = g * 45 + (size_t)head * 5;   // 180 floats / token
    const float   scale = 0.223606797749979f;          // 20^-0.5

    float4 q[5];
#pragma unroll
    for (int i = 0; i < 5; i++) {
        float4 t = qp[base4 + i];
        t.x *= scale; t.y *= scale; t.z *= scale; t.w *= scale;
        q[i] = t;
        ks [n][i] = qp[base4 + 15 + i];
        vsm[n][i] = qp[base4 + 30 + i];
    }
    int myreg = 0;
    if (shifted) {
        int rh = (hr  < Hc - wh) ? 0 : ((hr  < Hc - sh) ? 1 : 2);
        int rw = (wrr < Wc - ww) ? 0 : ((wrr < Wc - sw) ? 1 : 2);
        myreg = rh * 3 + rw;
        rg[n] = myreg;
    }
    __syncthreads();

    float4 acc[5];
#pragma unroll
    for (int i = 0; i < 5; i++) acc[i] = make_float4(0.f, 0.f, 0.f, 0.f);
    float denom = 0.f;

    if (shifted) {
        for (int m = 0; m < 256; m++) {
            float s = 0.f;
#pragma unroll
            for (int i = 0; i < 5; i++) {
                float4 kv = ks[m][i];
                s = fmaf(q[i].x, kv.x, s); s = fmaf(q[i].y, kv.y, s);
                s = fmaf(q[i].z, kv.z, s); s = fmaf(q[i].w, kv.w, s);
            }
            if (rg[m] != myreg) s -= 100.f;
            float p = __expf(s);
            denom += p;
#pragma unroll
            for (int i = 0; i < 5; i++) {
                float4 vv = vsm[m][i];
                acc[i].x = fmaf(p, vv.x, acc[i].x);
                acc[i].y = fmaf(p, vv.y, acc[i].y);
                acc[i].z = fmaf(p, vv.z, acc[i].z);
                acc[i].w = fmaf(p, vv.w, acc[i].w);
            }
        }
    } else {
        for (int m = 0; m < 256; m++) {
            float s = 0.f;
#pragma unroll
            for (int i = 0; i < 5; i++) {
                float4 kv = ks[m][i];
                s = fmaf(q[i].x, kv.x, s); s = fmaf(q[i].y, kv.y, s);
                s = fmaf(q[i].z, kv.z, s); s = fmaf(q[i].w, kv.w, s);
            }
            float p = __expf(s);
            denom += p;
#pragma unroll
            for (int i = 0; i < 5; i++) {
                float4 vv = vsm[m][i];
                acc[i].x = fmaf(p, vv.x, acc[i].x);
                acc[i].y = fmaf(p, vv.y, acc[i].y);
                acc[i].z = fmaf(p, vv.z, acc[i].z);
                acc[i].w = fmaf(p, vv.w, acc[i].w);
            }
        }
    }

    float inv = 1.f / denom;
    float4* op = (float4*)g_attn;
    size_t  ob = g * 15 + (size_t)head * 5;     // 60 floats / token
#pragma unroll
    for (int i = 0; i < 5; i++) {
        float4 t = acc[i];
        t.x *= inv; t.y *= inv; t.z *= inv; t.w *= inv;
        op[ob + i] = t;
    }
}

// ---------------------------------------------------------------------------
// conv3x3 60->12 + PixelShuffle(2) fused.
// ---------------------------------------------------------------------------
__global__ __launch_bounds__(256) void conv_out_k(
    const float* __restrict__ lw, const float* __restrict__ lb,
    float* __restrict__ out)
{
    const int TOT = Bn * 3 * 256 * 256;
    int idx = blockIdx.x * blockDim.x + threadIdx.x;
    if (idx >= TOT) return;
    int w2 = idx & 255;
    int h2 = (idx >> 8) & 255;
    int c  = (idx >> 16) % 3;
    int bb = idx / (3 * 65536);
    int co = c * 4 + (h2 & 1) * 2 + (w2 & 1);
    int h  = h2 >> 1, w = w2 >> 1;
    float acc = lb[co];
#pragma unroll
    for (int kh = 0; kh < 3; kh++) {
        int hh = h + kh - 1;
        if ((unsigned)hh >= (unsigned)Hc) continue;
#pragma unroll
        for (int kw = 0; kw < 3; kw++) {
            int ww2 = w + kw - 1;
            if ((unsigned)ww2 >= (unsigned)Wc) continue;
            const float* fp = g_feat + ((size_t)(bb * Hc + hh) * Wc + ww2) * Cch;
            const float* wp = lw + co * (Cch * 9) + kh * 3 + kw;
#pragma unroll
            for (int ci = 0; ci < Cch; ci++)
                acc = fmaf(fp[ci], wp[ci * 9], acc);
        }
    }
    out[idx] = acc;
}

// ---------------------------------------------------------------------------
// Launch
// ---------------------------------------------------------------------------
extern "C" void kernel_launch(void* const* d_in, const int* in_sizes, int n_in,
                              void* d_out, int out_size)
{
    (void)in_sizes; (void)n_in; (void)out_size;
    const float* x      = (const float*)d_in[0];
    const float* conv_w = (const float*)d_in[1];
    const float* conv_b = (const float*)d_in[2];
    const float* ln1_g  = (const float*)d_in[3];
    const float* ln1_b  = (const float*)d_in[4];
    const float* qkv_w  = (const float*)d_in[5];
    const float* qkv_b  = (const float*)d_in[6];
    const float* proj_w = (const float*)d_in[7];
    const float* proj_b = (const float*)d_in[8];
    const float* ln2_g  = (const float*)d_in[9];
    const float* ln2_b  = (const float*)d_in[10];
    const float* fc1_w  = (const float*)d_in[11];
    const float* fc1_b  = (const float*)d_in[12];
    const float* fc2_w  = (const float*)d_in[13];
    const float* fc2_b  = (const float*)d_in[14];
    const float* last_w = (const float*)d_in[15];
    const float* last_b = (const float*)d_in[16];
    float* out = (float*)d_out;

    // All GEMMs: MG=8 -> TM=32, XST=36, grid 1024.  (R8 geometry)
    // smem (floats): ws K*N + bs N [+ gs K + bt K + mu 32 + rs 32] + xs K*36
    constexpr int SM_QKV  = (60 * 180 + 180 + 120 + 64 + 60 * 36)  * 4;  // 53296
    constexpr int SM_FC1  = (60 * 120 + 120 + 120 + 64 + 60 * 36)  * 4;  // 38656
    constexpr int SM_PROJ = (60 * 60  + 60  + 60 * 36)  * 4;             // 23280
    constexpr int SM_FC2  = (120 * 60 + 60  + 120 * 36) * 4;             // 46320

    cudaFuncSetAttribute(ln_gemm_k<60, 180, 8, false, false, 384, 3>,
                         cudaFuncAttributeMaxDynamicSharedMemorySize, SM_QKV);
    cudaFuncSetAttribute(ln_gemm_k<60, 120, 8, true, true, 256, 4>,
                         cudaFuncAttributeMaxDynamicSharedMemorySize, SM_FC1);
    cudaFuncSetAttribute(gemm_resid_k<60, 60, 8, false, 128, 8>,
                         cudaFuncAttributeMaxDynamicSharedMemorySize, SM_PROJ);
    cudaFuncSetAttribute(gemm_resid_k<120, 60, 8, true, 128, 5>,
                         cudaFuncAttributeMaxDynamicSharedMemorySize, SM_FC2);

    conv_in_k<<<(NTOK * Cch + 255) / 256, 256>>>(x, conv_w, conv_b);

    for (int l = 0; l < NL; l++) {
        int i  = l % 6;
        int wi = i % 2;
        int wh = wi ? 8 : 32;
        int ww = wi ? 32 : 8;
        int shifted = (i % 4) >= 2;
        int sh = shifted ? (wi ? 4 : 16) : 0;
        int sw = shifted ? (wi ? 16 : 4) : 0;

        ln_gemm_k<60, 180, 8, false, false, 384, 3>
            <<<NTOK / 32, 384, SM_QKV>>>(ln1_g + l * 60, ln1_b + l * 60,
                                         qkv_w + (size_t)l * 60 * 180,
                                         qkv_b + l * 180);

        attn_k<<<dim3(Bn * 64, NHEADS), 256>>>(wh, ww, sh, sw, shifted);

        gemm_resid_k<60, 60, 8, false, 128, 8>
            <<<NTOK / 32, 128, SM_PROJ>>>(proj_w + (size_t)l * 3600,
                                          proj_b + l * 60);

        ln_gemm_k<60, 120, 8, true, true, 256, 4>
            <<<NTOK / 32, 256, SM_FC1>>>(ln2_g + l * 60, ln2_b + l * 60,
                                         fc1_w + (size_t)l * 7200,
                                         fc1_b + l * 120);

        gemm_resid_k<120, 60, 8, true, 128, 5>
            <<<NTOK / 32, 128, SM_FC2>>>(fc2_w + (size_t)l * 7200,
                                         fc2_b + l * 60);
    }

    conv_out_k<<<(Bn * 3 * 256 * 256 + 255) / 256, 256>>>(last_w, last_b, out);
}

// round 11
// speedup vs baseline: 1.2530x; 1.1490x over previous
#include <cuda_runtime.h>
#include <cstdint>

// ---------------------------------------------------------------------------
// SwinIR-lite forward: conv3x3(3->60) -> 36 x [LN+WindowAttn+res, LN+MLP+res]
// -> conv3x3(60->12) + PixelShuffle(2).  B=2, H=W=128, C=60.
// R11: all 4 GEMMs on tensor cores (tf32 mma.sync.m16n8k8, fp32 accumulate,
//      cvt.rna staging).  Attention / LN / convs stay fp32 (R10 form).
// ---------------------------------------------------------------------------

constexpr int Bn   = 2;
constexpr int Hc   = 128;
constexpr int Wc   = 128;
constexpr int Cch  = 60;
constexpr int NHEADS = 3;
constexpr int NTOK = Bn * Hc * Wc;          // 32768 tokens
constexpr int QKVC = 180;
constexpr int FCC  = 120;
constexpr int NL   = 36;

// Scratch (device globals; no allocation allowed)
__device__ float g_feat[NTOK * Cch];        // 7.5 MB
__device__ float g_qkv [NTOK * QKVC];       // 22.5 MB
__device__ float g_attn[NTOK * Cch];        // 7.5 MB
__device__ float g_mlp [NTOK * FCC];        // 15 MB

// ---- tf32 helpers ----------------------------------------------------------
__device__ __forceinline__ uint32_t f2tf(float v) {
    uint32_t r;
    asm("cvt.rna.tf32.f32 %0, %1;" : "=r"(r) : "f"(v));
    return r;
}
__device__ __forceinline__ void mma_tf32(float c[4],
    uint32_t a0, uint32_t a1, uint32_t a2, uint32_t a3,
    uint32_t b0, uint32_t b1)
{
    asm("mma.sync.aligned.m16n8k8.row.col.f32.tf32.tf32.f32 "
        "{%0,%1,%2,%3}, {%4,%5,%6,%7}, {%8,%9}, {%0,%1,%2,%3};"
        : "+f"(c[0]), "+f"(c[1]), "+f"(c[2]), "+f"(c[3])
        : "r"(a0), "r"(a1), "r"(a2), "r"(a3), "r"(b0), "r"(b1));
}

// ---------------------------------------------------------------------------
// conv3x3 3->60, NCHW in -> NHWC (token-major) out
// ---------------------------------------------------------------------------
__global__ __launch_bounds__(256) void conv_in_k(
    const float* __restrict__ x, const float* __restrict__ w,
    const float* __restrict__ b)
{
    int idx = blockIdx.x * blockDim.x + threadIdx.x;
    if (idx >= NTOK * Cch) return;
    int co = idx % Cch;
    int p  = idx / Cch;
    int wx = p % Wc;
    int hy = (p / Wc) % Hc;
    int bb = p / (Wc * Hc);
    float acc = b[co];
#pragma unroll
    for (int ci = 0; ci < 3; ci++) {
#pragma unroll
        for (int kh = 0; kh < 3; kh++) {
            int hh = hy + kh - 1;
            if ((unsigned)hh >= (unsigned)Hc) continue;
#pragma unroll
            for (int kw = 0; kw < 3; kw++) {
                int ww2 = wx + kw - 1;
                if ((unsigned)ww2 >= (unsigned)Wc) continue;
                acc += x[((bb * 3 + ci) * Hc + hh) * Wc + ww2] *
                       w[((co * 3 + ci) * 3 + kh) * 3 + kw];
            }
        }
    }
    g_feat[idx] = acc;
}

// ---------------------------------------------------------------------------
// Unified tf32 tensor-core GEMM:  Y[T,N] = op(X[T,K]) @ W[K,N] + bias
//   LNF   : apply LayerNorm(gamma,beta) to X rows first
//   SWISH : y *= sigmoid(y) after bias
//   SRC   : 0 = g_feat, 1 = g_attn, 2 = g_mlp
//   DST   : 0 = g_qkv (store), 1 = g_mlp (store), 2 = g_feat (+= residual)
// Block: 64 tokens, 256 threads, 8 warps = 4 mtiles x 2 nslabs (NT n8 each).
// Kp = K padded to KT*8 rows; Np = N padded to 2*NT*8 cols.
// XST % 32 == 4 (or 28), WST % 32 == 8 -> conflict-free fragment LDS.
// ---------------------------------------------------------------------------
template <int K, int Kp, int XST, int N, int Np, int WST, int NT, int KT,
          bool LNF, bool SWISH, int SRC, int DST, int MINB>
__global__ __launch_bounds__(256, MINB) void mma_gemm_k(
    const float* __restrict__ gamma, const float* __restrict__ beta,
    const float* __restrict__ w, const float* __restrict__ bias)
{
    extern __shared__ float sm[];
    float* ws   = sm;                    // Kp * WST   (tf32 bits)
    float* bs   = ws + Kp * WST;         // Np
    float* gs   = bs + Np;               // K
    float* bt   = gs + K;                // K
    float* mu_s = bt + K;                // 64
    float* rs_s = mu_s + 64;             // 64
    float* xs   = rs_s + 64;             // 64 * XST

    const int tid = threadIdx.x;
    const int T0  = blockIdx.x * 64;
    const float* src = (SRC == 0) ? g_feat : ((SRC == 1) ? g_attn : g_mlp);

    // ---- stage W (cvt to tf32), zero-pad rows [K,Kp) and cols [N,Np) ----
    {
        constexpr int NP4 = Np / 4;
        for (int i = tid; i < Kp * NP4; i += 256) {
            int row = i / NP4, c4 = (i % NP4) * 4;
            uint4 o = make_uint4(0u, 0u, 0u, 0u);
            if (row < K && c4 < N) {
                float4 v = *(const float4*)(w + (size_t)row * N + c4);
                o.x = f2tf(v.x); o.y = f2tf(v.y); o.z = f2tf(v.z); o.w = f2tf(v.w);
            }
            *(uint4*)(ws + row * WST + c4) = o;
        }
    }
    for (int i = tid; i < Np; i += 256) bs[i] = (i < N) ? bias[i] : 0.f;
    if (LNF)
        for (int i = tid; i < K; i += 256) { gs[i] = gamma[i]; bt[i] = beta[i]; }

    // ---- stage X (raw if LN; else cvt immediately), zero-pad cols [K,Kp) ----
    {
        constexpr int KP4 = Kp / 4;
        for (int i = tid; i < 64 * KP4; i += 256) {
            int row = i / KP4, c4 = (i % KP4) * 4;
            float4 v = make_float4(0.f, 0.f, 0.f, 0.f);
            if (c4 < K) v = *(const float4*)(src + (size_t)(T0 + row) * K + c4);
            if (LNF) {
                *(float4*)(xs + row * XST + c4) = v;
            } else {
                uint4 o;
                o.x = f2tf(v.x); o.y = f2tf(v.y); o.z = f2tf(v.z); o.w = f2tf(v.w);
                *(uint4*)(xs + row * XST + c4) = o;
            }
        }
    }
    __syncthreads();

    if (LNF) {
        if (tid < 64) {
            float s = 0.f, s2 = 0.f;
            for (int k = 0; k < K; k++) {
                float v = xs[tid * XST + k];
                s += v; s2 += v * v;
            }
            float mu  = s * (1.0f / K);
            float var = s2 * (1.0f / K) - mu * mu;
            mu_s[tid] = mu;
            rs_s[tid] = rsqrtf(var + 1e-5f);
        }
        __syncthreads();
        for (int i = tid; i < 64 * K; i += 256) {
            int row = i / K, k = i % K;
            float v = xs[row * XST + k];
            v = (v - mu_s[row]) * rs_s[row] * gs[k] + bt[k];
            xs[row * XST + k] = __uint_as_float(f2tf(v));
        }
        __syncthreads();
    }

    // ---- mma mainloop ----
    const int wid = tid >> 5, lane = tid & 31;
    const int mt = wid >> 1, ng = wid & 1;      // 4 mtiles x 2 nslabs
    const int g  = lane >> 2, tg = lane & 3;
    const int r0 = mt * 16 + g;

    float acc[NT][4];
#pragma unroll
    for (int nt = 0; nt < NT; nt++)
#pragma unroll
        for (int j = 0; j < 4; j++) acc[nt][j] = 0.f;

#pragma unroll
    for (int kt = 0; kt < KT; kt++) {
        const int k0 = kt * 8;
        uint32_t a0 = __float_as_uint(xs[r0 * XST + k0 + tg]);
        uint32_t a1 = __float_as_uint(xs[(r0 + 8) * XST + k0 + tg]);
        uint32_t a2 = __float_as_uint(xs[r0 * XST + k0 + tg + 4]);
        uint32_t a3 = __float_as_uint(xs[(r0 + 8) * XST + k0 + tg + 4]);
#pragma unroll
        for (int nt = 0; nt < NT; nt++) {
            const int nb = (ng * NT + nt) * 8 + g;
            uint32_t b0 = __float_as_uint(ws[(k0 + tg) * WST + nb]);
            uint32_t b1 = __float_as_uint(ws[(k0 + tg + 4) * WST + nb]);
            mma_tf32(acc[nt], a0, a1, a2, a3, b0, b1);
        }
    }

    // ---- epilogue ----
    const int gr0 = T0 + mt * 16 + g;
    const int gr1 = gr0 + 8;
#pragma unroll
    for (int nt = 0; nt < NT; nt++) {
        const int col = (ng * NT + nt) * 8 + 2 * tg;
        if (col < N) {                       // col even, N even -> pair safe
            float v0 = acc[nt][0] + bs[col];
            float v1 = acc[nt][1] + bs[col + 1];
            float v2 = acc[nt][2] + bs[col];
            float v3 = acc[nt][3] + bs[col + 1];
            if (SWISH) {
                v0 /= 1.f + __expf(-v0);  v1 /= 1.f + __expf(-v1);
                v2 /= 1.f + __expf(-v2);  v3 /= 1.f + __expf(-v3);
            }
            if (DST == 0) {
                *(float2*)(g_qkv + (size_t)gr0 * N + col) = make_float2(v0, v1);
                *(float2*)(g_qkv + (size_t)gr1 * N + col) = make_float2(v2, v3);
            } else if (DST == 1) {
                *(float2*)(g_mlp + (size_t)gr0 * N + col) = make_float2(v0, v1);
                *(float2*)(g_mlp + (size_t)gr1 * N + col) = make_float2(v2, v3);
            } else {
                float2 t0 = *(float2*)(g_feat + (size_t)gr0 * Cch + col);
                float2 t1 = *(float2*)(g_feat + (size_t)gr1 * Cch + col);
                t0.x += v0; t0.y += v1; t1.x += v2; t1.y += v3;
                *(float2*)(g_feat + (size_t)gr0 * Cch + col) = t0;
                *(float2*)(g_feat + (size_t)gr1 * Cch + col) = t1;
            }
        }
    }
}

// ---------------------------------------------------------------------------
// Window attention (R2 form).  Block = (window, head), 256 threads = queries.
// ---------------------------------------------------------------------------
__global__ __launch_bounds__(256) void attn_k(int wh, int ww, int sh, int sw,
                                              int shifted)
{
    __shared__ float4 ks [256][5];
    __shared__ float4 vsm[256][5];
    __shared__ int    rg [256];

    const int n    = threadIdx.x;
    const int head = blockIdx.y;
    const int win  = blockIdx.x;
    const int nW   = Wc / ww;
    const int perB = (Hc / wh) * nW;
    const int b    = win / perB;
    const int wr_  = win % perB;
    const int wy   = wr_ / nW, wx = wr_ % nW;
    const int iy   = n / ww,   ix = n % ww;
    const int hr   = wy * wh + iy;
    const int wrr  = wx * ww + ix;
    int hs = hr + sh;   if (hs  >= Hc) hs  -= Hc;
    int wsv = wrr + sw; if (wsv >= Wc) wsv -= Wc;
    const size_t g = ((size_t)b * Hc + hs) * Wc + wsv;

    const float4* qp    = (const float4*)g_qkv;
    const size_t  base4 = g * 45 + (size_t)head * 5;   // 180 floats / token
    const float   scale = 0.223606797749979f;          // 20^-0.5

    float4 q[5];
#pragma unroll
    for (int i = 0; i < 5; i++) {
        float4 t = qp[base4 + i];
        t.x *= scale; t.y *= scale; t.z *= scale; t.w *= scale;
        q[i] = t;
        ks [n][i] = qp[base4 + 15 + i];
        vsm[n][i] = qp[base4 + 30 + i];
    }
    int myreg = 0;
    if (shifted) {
        int rh = (hr  < Hc - wh) ? 0 : ((hr  < Hc - sh) ? 1 : 2);
        int rw = (wrr < Wc - ww) ? 0 : ((wrr < Wc - sw) ? 1 : 2);
        myreg = rh * 3 + rw;
        rg[n] = myreg;
    }
    __syncthreads();

    float4 acc[5];
#pragma unroll
    for (int i = 0; i < 5; i++) acc[i] = make_float4(0.f, 0.f, 0.f, 0.f);
    float denom = 0.f;

    if (shifted) {
        for (int m = 0; m < 256; m++) {
            float s = 0.f;
#pragma unroll
            for (int i = 0; i < 5; i++) {
                float4 kv = ks[m][i];
                s = fmaf(q[i].x, kv.x, s); s = fmaf(q[i].y, kv.y, s);
                s = fmaf(q[i].z, kv.z, s); s = fmaf(q[i].w, kv.w, s);
            }
            if (rg[m] != myreg) s -= 100.f;
            float p = __expf(s);
            denom += p;
#pragma unroll
            for (int i = 0; i < 5; i++) {
                float4 vv = vsm[m][i];
                acc[i].x = fmaf(p, vv.x, acc[i].x);
                acc[i].y = fmaf(p, vv.y, acc[i].y);
                acc[i].z = fmaf(p, vv.z, acc[i].z);
                acc[i].w = fmaf(p, vv.w, acc[i].w);
            }
        }
    } else {
        for (int m = 0; m < 256; m++) {
            float s = 0.f;
#pragma unroll
            for (int i = 0; i < 5; i++) {
                float4 kv = ks[m][i];
                s = fmaf(q[i].x, kv.x, s); s = fmaf(q[i].y, kv.y, s);
                s = fmaf(q[i].z, kv.z, s); s = fmaf(q[i].w, kv.w, s);
            }
            float p = __expf(s);
            denom += p;
#pragma unroll
            for (int i = 0; i < 5; i++) {
                float4 vv = vsm[m][i];
                acc[i].x = fmaf(p, vv.x, acc[i].x);
                acc[i].y = fmaf(p, vv.y, acc[i].y);
                acc[i].z = fmaf(p, vv.z, acc[i].z);
                acc[i].w = fmaf(p, vv.w, acc[i].w);
            }
        }
    }

    float inv = 1.f / denom;
    float4* op = (float4*)g_attn;
    size_t  ob = g * 15 + (size_t)head * 5;     // 60 floats / token
#pragma unroll
    for (int i = 0; i < 5; i++) {
        float4 t = acc[i];
        t.x *= inv; t.y *= inv; t.z *= inv; t.w *= inv;
        op[ob + i] = t;
    }
}

// ---------------------------------------------------------------------------
// conv3x3 60->12 + PixelShuffle(2) fused.
// ---------------------------------------------------------------------------
__global__ __launch_bounds__(256) void conv_out_k(
    const float* __restrict__ lw, const float* __restrict__ lb,
    float* __restrict__ out)
{
    const int TOT = Bn * 3 * 256 * 256;
    int idx = blockIdx.x * blockDim.x + threadIdx.x;
    if (idx >= TOT) return;
    int w2 = idx & 255;
    int h2 = (idx >> 8) & 255;
    int c  = (idx >> 16) % 3;
    int bb = idx / (3 * 65536);
    int co = c * 4 + (h2 & 1) * 2 + (w2 & 1);
    int h  = h2 >> 1, w = w2 >> 1;
    float acc = lb[co];
#pragma unroll
    for (int kh = 0; kh < 3; kh++) {
        int hh = h + kh - 1;
        if ((unsigned)hh >= (unsigned)Hc) continue;
#pragma unroll
        for (int kw = 0; kw < 3; kw++) {
            int ww2 = w + kw - 1;
            if ((unsigned)ww2 >= (unsigned)Wc) continue;
            const float* fp = g_feat + ((size_t)(bb * Hc + hh) * Wc + ww2) * Cch;
            const float* wp = lw + co * (Cch * 9) + kh * 3 + kw;
#pragma unroll
            for (int ci = 0; ci < Cch; ci++)
                acc = fmaf(fp[ci], wp[ci * 9], acc);
        }
    }
    out[idx] = acc;
}

// ---------------------------------------------------------------------------
// Launch
// ---------------------------------------------------------------------------

// smem sizes (floats): Kp*WST + Np + 2K + 128 + 64*XST
constexpr int smf(int K, int Kp, int XST, int Np, int WST) {
    return Kp * WST + Np + 2 * K + 128 + 64 * XST;
}

extern "C" void kernel_launch(void* const* d_in, const int* in_sizes, int n_in,
                              void* d_out, int out_size)
{
    (void)in_sizes; (void)n_in; (void)out_size;
    const float* x      = (const float*)d_in[0];
    const float* conv_w = (const float*)d_in[1];
    const float* conv_b = (const float*)d_in[2];
    const float* ln1_g  = (const float*)d_in[3];
    const float* ln1_b  = (const float*)d_in[4];
    const float* qkv_w  = (const float*)d_in[5];
    const float* qkv_b  = (const float*)d_in[6];
    const float* proj_w = (const float*)d_in[7];
    const float* proj_b = (const float*)d_in[8];
    const float* ln2_g  = (const float*)d_in[9];
    const float* ln2_b  = (const float*)d_in[10];
    const float* fc1_w  = (const float*)d_in[11];
    const float* fc1_b  = (const float*)d_in[12];
    const float* fc2_w  = (const float*)d_in[13];
    const float* fc2_b  = (const float*)d_in[14];
    const float* last_w = (const float*)d_in[15];
    const float* last_b = (const float*)d_in[16];
    float* out = (float*)d_out;

    // template args: K, Kp, XST, N, Np, WST, NT, KT, LNF, SWISH, SRC, DST, MINB
    // qkv : 60,64,68, 180,192,200, 12,8, LN,  -,    feat, qkv,  3   smem 70368B
    // fc1 : 60,64,68, 120,128,136,  8,8, LN,  swish,feat, mlp,  4   smem 53728B
    // proj: 60,64,68,  60, 64, 72,  4,8, -,   -,    attn, feat, 4   smem 37088B
    // fc2 :120,120,124,60, 64, 72,  4,15,-,   -,    mlp,  feat, 3   smem 68032B
    constexpr int SM_QKV  = smf(60, 64, 68, 192, 200) * 4;
    constexpr int SM_FC1  = smf(60, 64, 68, 128, 136) * 4;
    constexpr int SM_PROJ = smf(60, 64, 68, 64, 72) * 4;
    constexpr int SM_FC2  = smf(120, 120, 124, 64, 72) * 4;

    cudaFuncSetAttribute(
        mma_gemm_k<60, 64, 68, 180, 192, 200, 12, 8, true, false, 0, 0, 3>,
        cudaFuncAttributeMaxDynamicSharedMemorySize, SM_QKV);
    cudaFuncSetAttribute(
        mma_gemm_k<60, 64, 68, 120, 128, 136, 8, 8, true, true, 0, 1, 4>,
        cudaFuncAttributeMaxDynamicSharedMemorySize, SM_FC1);
    cudaFuncSetAttribute(
        mma_gemm_k<60, 64, 68, 60, 64, 72, 4, 8, false, false, 1, 2, 4>,
        cudaFuncAttributeMaxDynamicSharedMemorySize, SM_PROJ);
    cudaFuncSetAttribute(
        mma_gemm_k<120, 120, 124, 60, 64, 72, 4, 15, false, false, 2, 2, 3>,
        cudaFuncAttributeMaxDynamicSharedMemorySize, SM_FC2);

    conv_in_k<<<(NTOK * Cch + 255) / 256, 256>>>(x, conv_w, conv_b);

    const int GG = NTOK / 64;   // 512

    for (int l = 0; l < NL; l++) {
        int i  = l % 6;
        int wi = i % 2;
        int wh = wi ? 8 : 32;
        int ww = wi ? 32 : 8;
        int shifted = (i % 4) >= 2;
        int sh = shifted ? (wi ? 4 : 16) : 0;
        int sw = shifted ? (wi ? 16 : 4) : 0;

        mma_gemm_k<60, 64, 68, 180, 192, 200, 12, 8, true, false, 0, 0, 3>
            <<<GG, 256, SM_QKV>>>(ln1_g + l * 60, ln1_b + l * 60,
                                  qkv_w + (size_t)l * 60 * 180,
                                  qkv_b + l * 180);

        attn_k<<<dim3(Bn * 64, NHEADS), 256>>>(wh, ww, sh, sw, shifted);

        mma_gemm_k<60, 64, 68, 60, 64, 72, 4, 8, false, false, 1, 2, 4>
            <<<GG, 256, SM_PROJ>>>(nullptr, nullptr,
                                   proj_w + (size_t)l * 3600,
                                   proj_b + l * 60);

        mma_gemm_k<60, 64, 68, 120, 128, 136, 8, 8, true, true, 0, 1, 4>
            <<<GG, 256, SM_FC1>>>(ln2_g + l * 60, ln2_b + l * 60,
                                  fc1_w + (size_t)l * 7200,
                                  fc1_b + l * 120);

        mma_gemm_k<120, 120, 124, 60, 64, 72, 4, 15, false, false, 2, 2, 3>
            <<<GG, 256, SM_FC2>>>(nullptr, nullptr,
                                  fc2_w + (size_t)l * 7200,
                                  fc2_b + l * 60);
    }

    conv_out_k<<<(Bn * 3 * 256 * 256 + 255) / 256, 256>>>(last_w, last_b, out);
}

// round 14
// speedup vs baseline: 1.7871x; 1.4263x over previous
#include <cuda_runtime.h>
#include <cstdint>

// ---------------------------------------------------------------------------
// SwinIR-lite forward: conv3x3(3->60) -> 36 x [LN+WindowAttn+res, LN+MLP+res]
// -> conv3x3(60->12) + PixelShuffle(2).  B=2, H=W=128, C=60.
// R12 (third submit; two broker-level failures, code audit clean: fixed-trip
// loops only, aligned smem/gmem accesses, mechanisms identical to passing
// R11): R11 tf32 GEMMs kept; attention on tensor cores (flash-style:
// QK^T mma -> exp/mask fp32 -> P@V mma, no max-subtract).
// ---------------------------------------------------------------------------

constexpr int Bn   = 2;
constexpr int Hc   = 128;
constexpr int Wc   = 128;
constexpr int Cch  = 60;
constexpr int NHEADS = 3;
constexpr int NTOK = Bn * Hc * Wc;          // 32768 tokens
constexpr int QKVC = 180;
constexpr int FCC  = 120;
constexpr int NL   = 36;

// Scratch (device globals; no allocation allowed)
__device__ float g_feat[NTOK * Cch];        // 7.5 MB
__device__ float g_qkv [NTOK * QKVC];       // 22.5 MB
__device__ float g_attn[NTOK * Cch];        // 7.5 MB
__device__ float g_mlp [NTOK * FCC];        // 15 MB

// ---- tf32 helpers ----------------------------------------------------------
__device__ __forceinline__ uint32_t f2tf(float v) {
    uint32_t r;
    asm("cvt.rna.tf32.f32 %0, %1;" : "=r"(r) : "f"(v));
    return r;
}
__device__ __forceinline__ void mma_tf32(float c[4],
    uint32_t a0, uint32_t a1, uint32_t a2, uint32_t a3,
    uint32_t b0, uint32_t b1)
{
    asm("mma.sync.aligned.m16n8k8.row.col.f32.tf32.tf32.f32 "
        "{%0,%1,%2,%3}, {%4,%5,%6,%7}, {%8,%9}, {%0,%1,%2,%3};"
        : "+f"(c[0]), "+f"(c[1]), "+f"(c[2]), "+f"(c[3])
        : "r"(a0), "r"(a1), "r"(a2), "r"(a3), "r"(b0), "r"(b1));
}

// ---------------------------------------------------------------------------
// conv3x3 3->60, NCHW in -> NHWC (token-major) out
// ---------------------------------------------------------------------------
__global__ __launch_bounds__(256) void conv_in_k(
    const float* __restrict__ x, const float* __restrict__ w,
    const float* __restrict__ b)
{
    int idx = blockIdx.x * blockDim.x + threadIdx.x;
    if (idx >= NTOK * Cch) return;
    int co = idx % Cch;
    int p  = idx / Cch;
    int wx = p % Wc;
    int hy = (p / Wc) % Hc;
    int bb = p / (Wc * Hc);
    float acc = b[co];
#pragma unroll
    for (int ci = 0; ci < 3; ci++) {
#pragma unroll
        for (int kh = 0; kh < 3; kh++) {
            int hh = hy + kh - 1;
            if ((unsigned)hh >= (unsigned)Hc) continue;
#pragma unroll
            for (int kw = 0; kw < 3; kw++) {
                int ww2 = wx + kw - 1;
                if ((unsigned)ww2 >= (unsigned)Wc) continue;
                acc += x[((bb * 3 + ci) * Hc + hh) * Wc + ww2] *
                       w[((co * 3 + ci) * 3 + kh) * 3 + kw];
            }
        }
    }
    g_feat[idx] = acc;
}

// ---------------------------------------------------------------------------
// Unified tf32 tensor-core GEMM (unchanged from R11).
// ---------------------------------------------------------------------------
template <int K, int Kp, int XST, int N, int Np, int WST, int NT, int KT,
          bool LNF, bool SWISH, int SRC, int DST, int MINB>
__global__ __launch_bounds__(256, MINB) void mma_gemm_k(
    const float* __restrict__ gamma, const float* __restrict__ beta,
    const float* __restrict__ w, const float* __restrict__ bias)
{
    extern __shared__ float sm[];
    float* ws   = sm;                    // Kp * WST   (tf32 bits)
    float* bs   = ws + Kp * WST;         // Np
    float* gs   = bs + Np;               // K
    float* bt   = gs + K;                // K
    float* mu_s = bt + K;                // 64
    float* rs_s = mu_s + 64;             // 64
    float* xs   = rs_s + 64;             // 64 * XST

    const int tid = threadIdx.x;
    const int T0  = blockIdx.x * 64;
    const float* src = (SRC == 0) ? g_feat : ((SRC == 1) ? g_attn : g_mlp);

    {
        constexpr int NP4 = Np / 4;
        for (int i = tid; i < Kp * NP4; i += 256) {
            int row = i / NP4, c4 = (i % NP4) * 4;
            uint4 o = make_uint4(0u, 0u, 0u, 0u);
            if (row < K && c4 < N) {
                float4 v = *(const float4*)(w + (size_t)row * N + c4);
                o.x = f2tf(v.x); o.y = f2tf(v.y); o.z = f2tf(v.z); o.w = f2tf(v.w);
            }
            *(uint4*)(ws + row * WST + c4) = o;
        }
    }
    for (int i = tid; i < Np; i += 256) bs[i] = (i < N) ? bias[i] : 0.f;
    if (LNF)
        for (int i = tid; i < K; i += 256) { gs[i] = gamma[i]; bt[i] = beta[i]; }

    {
        constexpr int KP4 = Kp / 4;
        for (int i = tid; i < 64 * KP4; i += 256) {
            int row = i / KP4, c4 = (i % KP4) * 4;
            float4 v = make_float4(0.f, 0.f, 0.f, 0.f);
            if (c4 < K) v = *(const float4*)(src + (size_t)(T0 + row) * K + c4);
            if (LNF) {
                *(float4*)(xs + row * XST + c4) = v;
            } else {
                uint4 o;
                o.x = f2tf(v.x); o.y = f2tf(v.y); o.z = f2tf(v.z); o.w = f2tf(v.w);
                *(uint4*)(xs + row * XST + c4) = o;
            }
        }
    }
    __syncthreads();

    if (LNF) {
        if (tid < 64) {
            float s = 0.f, s2 = 0.f;
            for (int k = 0; k < K; k++) {
                float v = xs[tid * XST + k];
                s += v; s2 += v * v;
            }
            float mu  = s * (1.0f / K);
            float var = s2 * (1.0f / K) - mu * mu;
            mu_s[tid] = mu;
            rs_s[tid] = rsqrtf(var + 1e-5f);
        }
        __syncthreads();
        for (int i = tid; i < 64 * K; i += 256) {
            int row = i / K, k = i % K;
            float v = xs[row * XST + k];
            v = (v - mu_s[row]) * rs_s[row] * gs[k] + bt[k];
            xs[row * XST + k] = __uint_as_float(f2tf(v));
        }
        __syncthreads();
    }

    const int wid = tid >> 5, lane = tid & 31;
    const int mt = wid >> 1, ng = wid & 1;
    const int g  = lane >> 2, tg = lane & 3;
    const int r0 = mt * 16 + g;

    float acc[NT][4];
#pragma unroll
    for (int nt = 0; nt < NT; nt++)
#pragma unroll
        for (int j = 0; j < 4; j++) acc[nt][j] = 0.f;

#pragma unroll
    for (int kt = 0; kt < KT; kt++) {
        const int k0 = kt * 8;
        uint32_t a0 = __float_as_uint(xs[r0 * XST + k0 + tg]);
        uint32_t a1 = __float_as_uint(xs[(r0 + 8) * XST + k0 + tg]);
        uint32_t a2 = __float_as_uint(xs[r0 * XST + k0 + tg + 4]);
        uint32_t a3 = __float_as_uint(xs[(r0 + 8) * XST + k0 + tg + 4]);
#pragma unroll
        for (int nt = 0; nt < NT; nt++) {
            const int nb = (ng * NT + nt) * 8 + g;
            uint32_t b0 = __float_as_uint(ws[(k0 + tg) * WST + nb]);
            uint32_t b1 = __float_as_uint(ws[(k0 + tg + 4) * WST + nb]);
            mma_tf32(acc[nt], a0, a1, a2, a3, b0, b1);
        }
    }

    const int gr0 = T0 + mt * 16 + g;
    const int gr1 = gr0 + 8;
#pragma unroll
    for (int nt = 0; nt < NT; nt++) {
        const int col = (ng * NT + nt) * 8 + 2 * tg;
        if (col < N) {
            float v0 = acc[nt][0] + bs[col];
            float v1 = acc[nt][1] + bs[col + 1];
            float v2 = acc[nt][2] + bs[col];
            float v3 = acc[nt][3] + bs[col + 1];
            if (SWISH) {
                v0 /= 1.f + __expf(-v0);  v1 /= 1.f + __expf(-v1);
                v2 /= 1.f + __expf(-v2);  v3 /= 1.f + __expf(-v3);
            }
            if (DST == 0) {
                *(float2*)(g_qkv + (size_t)gr0 * N + col) = make_float2(v0, v1);
                *(float2*)(g_qkv + (size_t)gr1 * N + col) = make_float2(v2, v3);
            } else if (DST == 1) {
                *(float2*)(g_mlp + (size_t)gr0 * N + col) = make_float2(v0, v1);
                *(float2*)(g_mlp + (size_t)gr1 * N + col) = make_float2(v2, v3);
            } else {
                float2 t0 = *(float2*)(g_feat + (size_t)gr0 * Cch + col);
                float2 t1 = *(float2*)(g_feat + (size_t)gr1 * Cch + col);
                t0.x += v0; t0.y += v1; t1.x += v2; t1.y += v3;
                *(float2*)(g_feat + (size_t)gr0 * Cch + col) = t0;
                *(float2*)(g_feat + (size_t)gr1 * Cch + col) = t1;
            }
        }
    }
}

// ---------------------------------------------------------------------------
// Tensor-core window attention.  Block = (window, head), 256 thr = 8 warps.
// Warp w owns query rows [32w, 32w+32) as 2 m16 tiles.  Keys looped in 8
// chunks of 32.  QK^T and P@V on tf32 mma; mask/exp/denom fp32.
// smem: K(256x28 tf32) V(256x24 tf32) P(256x36 tf32; Q staged here first)
//       tok[256] rg[256]   = 92160 B -> 2 blocks/SM.
// ---------------------------------------------------------------------------
__global__ __launch_bounds__(256, 2) void attn_mma_k(int wh, int ww,
                                                     int sh, int sw,
                                                     int shifted)
{
    constexpr int KST = 28, VST = 24, PST = 36;
    extern __shared__ float asm_[];
    float* k_s   = asm_;                    // 256*28
    float* v_s   = k_s + 256 * KST;         // 256*24
    float* p_s   = v_s + 256 * VST;         // 256*36 (Q staging first)
    int*   tok_s = (int*)(p_s + 256 * PST); // 256
    int*   rg_s  = tok_s + 256;             // 256

    const int tid  = threadIdx.x;
    const int wid  = tid >> 5, lane = tid & 31;
    const int g    = lane >> 2, tg = lane & 3;
    const int head = blockIdx.y;
    const int win  = blockIdx.x;
    const int nW   = Wc / ww;
    const int perB = (Hc / wh) * nW;
    const int b    = win / perB;
    const int wr_  = win % perB;
    const int wy   = wr_ / nW, wx = wr_ % nW;

    // ---- stage one row per thread ----
    {
        const int n  = tid;
        const int iy = n / ww, ix = n % ww;
        const int hr = wy * wh + iy;
        const int wr = wx * ww + ix;
        int hs = hr + sh;  if (hs >= Hc) hs -= Hc;
        int ws2 = wr + sw; if (ws2 >= Wc) ws2 -= Wc;
        const int tok = (b * Hc + hs) * Wc + ws2;
        tok_s[n] = tok;
        if (shifted) {
            int rh = (hr < Hc - wh) ? 0 : ((hr < Hc - sh) ? 1 : 2);
            int rw = (wr < Wc - ww) ? 0 : ((wr < Wc - sw) ? 1 : 2);
            rg_s[n] = rh * 3 + rw;
        }
        const float4* qp = (const float4*)g_qkv;
        const size_t base4 = (size_t)tok * 45 + (size_t)head * 5;
        const float scale = 0.223606797749979f;   // 20^-0.5
#pragma unroll
        for (int i = 0; i < 5; i++) {
            float4 q = qp[base4 + i];
            float4 k = qp[base4 + 15 + i];
            float4 v = qp[base4 + 30 + i];
            uint4 qo, ko, vo;
            qo.x = f2tf(q.x * scale); qo.y = f2tf(q.y * scale);
            qo.z = f2tf(q.z * scale); qo.w = f2tf(q.w * scale);
            ko.x = f2tf(k.x); ko.y = f2tf(k.y); ko.z = f2tf(k.z); ko.w = f2tf(k.w);
            vo.x = f2tf(v.x); vo.y = f2tf(v.y); vo.z = f2tf(v.z); vo.w = f2tf(v.w);
            // strides 28/28/24 not 16B-aligned per row -> scalar stores
            p_s[n * KST + 4 * i + 0] = __uint_as_float(qo.x);
            p_s[n * KST + 4 * i + 1] = __uint_as_float(qo.y);
            p_s[n * KST + 4 * i + 2] = __uint_as_float(qo.z);
            p_s[n * KST + 4 * i + 3] = __uint_as_float(qo.w);
            k_s[n * KST + 4 * i + 0] = __uint_as_float(ko.x);
            k_s[n * KST + 4 * i + 1] = __uint_as_float(ko.y);
            k_s[n * KST + 4 * i + 2] = __uint_as_float(ko.z);
            k_s[n * KST + 4 * i + 3] = __uint_as_float(ko.w);
            v_s[n * VST + 4 * i + 0] = __uint_as_float(vo.x);
            v_s[n * VST + 4 * i + 1] = __uint_as_float(vo.y);
            v_s[n * VST + 4 * i + 2] = __uint_as_float(vo.z);
            v_s[n * VST + 4 * i + 3] = __uint_as_float(vo.w);
        }
#pragma unroll
        for (int c = 20; c < 24; c++) {     // zero pads (kt=2 reads cols 20..23)
            p_s[n * KST + c] = 0.f;
            k_s[n * KST + c] = 0.f;
            v_s[n * VST + c] = 0.f;
        }
    }
    __syncthreads();

    // ---- preload Q fragments (rows fixed per warp) ----
    const int wr0 = wid * 32;
    uint32_t qf[2][3][4];
    int rgA[2], rgB[2];
#pragma unroll
    for (int mt = 0; mt < 2; mt++) {
        const int r0 = wr0 + mt * 16 + g;
#pragma unroll
        for (int kt = 0; kt < 3; kt++) {
            const int c = kt * 8 + tg;
            qf[mt][kt][0] = __float_as_uint(p_s[r0 * KST + c]);
            qf[mt][kt][1] = __float_as_uint(p_s[(r0 + 8) * KST + c]);
            qf[mt][kt][2] = __float_as_uint(p_s[r0 * KST + c + 4]);
            qf[mt][kt][3] = __float_as_uint(p_s[(r0 + 8) * KST + c + 4]);
        }
        if (shifted) { rgA[mt] = rg_s[r0]; rgB[mt] = rg_s[r0 + 8]; }
    }
    __syncthreads();   // Q reads done; p_s now reused for P chunks

    float oacc[2][3][4];
#pragma unroll
    for (int mt = 0; mt < 2; mt++)
#pragma unroll
        for (int nt = 0; nt < 3; nt++)
#pragma unroll
            for (int j = 0; j < 4; j++) oacc[mt][nt][j] = 0.f;
    float dsum[2][2] = {{0.f, 0.f}, {0.f, 0.f}};

    for (int c = 0; c < 8; c++) {           // key chunks of 32
        const int kb = c * 32;
#pragma unroll
        for (int mt = 0; mt < 2; mt++) {
            float sacc[4][4];
#pragma unroll
            for (int nt = 0; nt < 4; nt++)
#pragma unroll
                for (int j = 0; j < 4; j++) sacc[nt][j] = 0.f;
#pragma unroll
            for (int kt = 0; kt < 3; kt++) {
                const int k0 = kt * 8;
#pragma unroll
                for (int nt = 0; nt < 4; nt++) {
                    const int nb = kb + nt * 8 + g;
                    uint32_t b0 = __float_as_uint(k_s[nb * KST + k0 + tg]);
                    uint32_t b1 = __float_as_uint(k_s[nb * KST + k0 + tg + 4]);
                    mma_tf32(sacc[nt], qf[mt][kt][0], qf[mt][kt][1],
                             qf[mt][kt][2], qf[mt][kt][3], b0, b1);
                }
            }
            const int r0 = wr0 + mt * 16 + g;
#pragma unroll
            for (int nt = 0; nt < 4; nt++) {
                const int col0 = kb + nt * 8 + 2 * tg;
                float s0 = sacc[nt][0], s1 = sacc[nt][1];
                float s2 = sacc[nt][2], s3 = sacc[nt][3];
                if (shifted) {
                    int rc0 = rg_s[col0], rc1 = rg_s[col0 + 1];
                    if (rc0 != rgA[mt]) s0 -= 100.f;
                    if (rc1 != rgA[mt]) s1 -= 100.f;
                    if (rc0 != rgB[mt]) s2 -= 100.f;
                    if (rc1 != rgB[mt]) s3 -= 100.f;
                }
                float p0 = __expf(s0), p1 = __expf(s1);
                float p2 = __expf(s2), p3 = __expf(s3);
                dsum[mt][0] += p0 + p1;
                dsum[mt][1] += p2 + p3;
                uint2 u0 = make_uint2(f2tf(p0), f2tf(p1));
                uint2 u1 = make_uint2(f2tf(p2), f2tf(p3));
                *(uint2*)(p_s + r0 * PST + nt * 8 + 2 * tg)       = u0;
                *(uint2*)(p_s + (r0 + 8) * PST + nt * 8 + 2 * tg) = u1;
            }
        }
        __syncwarp();
#pragma unroll
        for (int kt2 = 0; kt2 < 4; kt2++) {
            const int kr = kb + kt2 * 8;
#pragma unroll
            for (int mt = 0; mt < 2; mt++) {
                const int r0 = wr0 + mt * 16 + g;
                uint32_t a0 = __float_as_uint(p_s[r0 * PST + kt2 * 8 + tg]);
                uint32_t a1 = __float_as_uint(p_s[(r0 + 8) * PST + kt2 * 8 + tg]);
                uint32_t a2 = __float_as_uint(p_s[r0 * PST + kt2 * 8 + tg + 4]);
                uint32_t a3 = __float_as_uint(p_s[(r0 + 8) * PST + kt2 * 8 + tg + 4]);
#pragma unroll
                for (int nt = 0; nt < 3; nt++) {
                    const int nb = nt * 8 + g;
                    uint32_t b0 = __float_as_uint(v_s[(kr + tg) * VST + nb]);
                    uint32_t b1 = __float_as_uint(v_s[(kr + tg + 4) * VST + nb]);
                    mma_tf32(oacc[mt][nt], a0, a1, a2, a3, b0, b1);
                }
            }
        }
        __syncwarp();
    }

    // ---- denominators: reduce across quad (lanes share rows) ----
    float inv[2][2];
#pragma unroll
    for (int mt = 0; mt < 2; mt++)
#pragma unroll
        for (int j = 0; j < 2; j++) {
            float d = dsum[mt][j];
            d += __shfl_xor_sync(0xFFFFFFFFu, d, 1);
            d += __shfl_xor_sync(0xFFFFFFFFu, d, 2);
            inv[mt][j] = 1.f / d;
        }

    // ---- epilogue ----
#pragma unroll
    for (int mt = 0; mt < 2; mt++) {
        const int r0 = wr0 + mt * 16 + g;
        const int tok0 = tok_s[r0];
        const int tok1 = tok_s[r0 + 8];
#pragma unroll
        for (int nt = 0; nt < 3; nt++) {
            const int col = nt * 8 + 2 * tg;
            if (col < 20) {
                float2 w0 = make_float2(oacc[mt][nt][0] * inv[mt][0],
                                        oacc[mt][nt][1] * inv[mt][0]);
                float2 w1 = make_float2(oacc[mt][nt][2] * inv[mt][1],
                                        oacc[mt][nt][3] * inv[mt][1]);
                *(float2*)(g_attn + (size_t)tok0 * Cch + head * 20 + col) = w0;
                *(float2*)(g_attn + (size_t)tok1 * Cch + head * 20 + col) = w1;
            }
        }
    }
}

// ---------------------------------------------------------------------------
// conv3x3 60->12 + PixelShuffle(2) fused.
// ---------------------------------------------------------------------------
__global__ __launch_bounds__(256) void conv_out_k(
    const float* __restrict__ lw, const float* __restrict__ lb,
    float* __restrict__ out)
{
    const int TOT = Bn * 3 * 256 * 256;
    int idx = blockIdx.x * blockDim.x + threadIdx.x;
    if (idx >= TOT) return;
    int w2 = idx & 255;
    int h2 = (idx >> 8) & 255;
    int c  = (idx >> 16) % 3;
    int bb = idx / (3 * 65536);
    int co = c * 4 + (h2 & 1) * 2 + (w2 & 1);
    int h  = h2 >> 1, w = w2 >> 1;
    float acc = lb[co];
#pragma unroll
    for (int kh = 0; kh < 3; kh++) {
        int hh = h + kh - 1;
        if ((unsigned)hh >= (unsigned)Hc) continue;
#pragma unroll
        for (int kw = 0; kw < 3; kw++) {
            int ww2 = w + kw - 1;
            if ((unsigned)ww2 >= (unsigned)Wc) continue;
            const float* fp = g_feat + ((size_t)(bb * Hc + hh) * Wc + ww2) * Cch;
            const float* wp = lw + co * (Cch * 9) + kh * 3 + kw;
#pragma unroll
            for (int ci = 0; ci < Cch; ci++)
                acc = fmaf(fp[ci], wp[ci * 9], acc);
        }
    }
    out[idx] = acc;
}

// ---------------------------------------------------------------------------
// Launch
// ---------------------------------------------------------------------------

constexpr int smf(int K, int Kp, int XST, int Np, int WST) {
    return Kp * WST + Np + 2 * K + 128 + 64 * XST;
}

extern "C" void kernel_launch(void* const* d_in, const int* in_sizes, int n_in,
                              void* d_out, int out_size)
{
    (void)in_sizes; (void)n_in; (void)out_size;
    const float* x      = (const float*)d_in[0];
    const float* conv_w = (const float*)d_in[1];
    const float* conv_b = (const float*)d_in[2];
    const float* ln1_g  = (const float*)d_in[3];
    const float* ln1_b  = (const float*)d_in[4];
    const float* qkv_w  = (const float*)d_in[5];
    const float* qkv_b  = (const float*)d_in[6];
    const float* proj_w = (const float*)d_in[7];
    const float* proj_b = (const float*)d_in[8];
    const float* ln2_g  = (const float*)d_in[9];
    const float* ln2_b  = (const float*)d_in[10];
    const float* fc1_w  = (const float*)d_in[11];
    const float* fc1_b  = (const float*)d_in[12];
    const float* fc2_w  = (const float*)d_in[13];
    const float* fc2_b  = (const float*)d_in[14];
    const float* last_w = (const float*)d_in[15];
    const float* last_b = (const float*)d_in[16];
    float* out = (float*)d_out;

    constexpr int SM_QKV  = smf(60, 64, 68, 192, 200) * 4;
    constexpr int SM_FC1  = smf(60, 64, 68, 128, 136) * 4;
    constexpr int SM_PROJ = smf(60, 64, 68, 64, 72) * 4;
    constexpr int SM_FC2  = smf(120, 120, 124, 64, 72) * 4;
    constexpr int SM_ATTN = (256 * 28 + 256 * 24 + 256 * 36 + 512) * 4;  // 92160

    cudaFuncSetAttribute(
        mma_gemm_k<60, 64, 68, 180, 192, 200, 12, 8, true, false, 0, 0, 3>,
        cudaFuncAttributeMaxDynamicSharedMemorySize, SM_QKV);
    cudaFuncSetAttribute(
        mma_gemm_k<60, 64, 68, 120, 128, 136, 8, 8, true, true, 0, 1, 4>,
        cudaFuncAttributeMaxDynamicSharedMemorySize, SM_FC1);
    cudaFuncSetAttribute(
        mma_gemm_k<60, 64, 68, 60, 64, 72, 4, 8, false, false, 1, 2, 4>,
        cudaFuncAttributeMaxDynamicSharedMemorySize, SM_PROJ);
    cudaFuncSetAttribute(
        mma_gemm_k<120, 120, 124, 60, 64, 72, 4, 15, false, false, 2, 2, 3>,
        cudaFuncAttributeMaxDynamicSharedMemorySize, SM_FC2);
    cudaFuncSetAttribute(attn_mma_k,
        cudaFuncAttributeMaxDynamicSharedMemorySize, SM_ATTN);

    conv_in_k<<<(NTOK * Cch + 255) / 256, 256>>>(x, conv_w, conv_b);

    const int GG = NTOK / 64;   // 512

    for (int l = 0; l < NL; l++) {
        int i  = l % 6;
        int wi = i % 2;
        int wh = wi ? 8 : 32;
        int ww = wi ? 32 : 8;
        int shifted = (i % 4) >= 2;
        int sh = shifted ? (wi ? 4 : 16) : 0;
        int sw = shifted ? (wi ? 16 : 4) : 0;

        mma_gemm_k<60, 64, 68, 180, 192, 200, 12, 8, true, false, 0, 0, 3>
            <<<GG, 256, SM_QKV>>>(ln1_g + l * 60, ln1_b + l * 60,
                                  qkv_w + (size_t)l * 60 * 180,
                                  qkv_b + l * 180);

        attn_mma_k<<<dim3(Bn * 64, NHEADS), 256, SM_ATTN>>>(wh, ww, sh, sw,
                                                            shifted);

        mma_gemm_k<60, 64, 68, 60, 64, 72, 4, 8, false, false, 1, 2, 4>
            <<<GG, 256, SM_PROJ>>>(nullptr, nullptr,
                                   proj_w + (size_t)l * 3600,
                                   proj_b + l * 60);

        mma_gemm_k<60, 64, 68, 120, 128, 136, 8, 8, true, true, 0, 1, 4>
            <<<GG, 256, SM_FC1>>>(ln2_g + l * 60, ln2_b + l * 60,
                                  fc1_w + (size_t)l * 7200,
                                  fc1_b + l * 120);

        mma_gemm_k<120, 120, 124, 60, 64, 72, 4, 15, false, false, 2, 2, 3>
            <<<GG, 256, SM_FC2>>>(nullptr, nullptr,
                                  fc2_w + (size_t)l * 7200,
                                  fc2_b + l * 60);
    }

    conv_out_k<<<(Bn * 3 * 256 * 256 + 255) / 256, 256>>>(last_w, last_b, out);
}

// round 15
// speedup vs baseline: 1.9547x; 1.0938x over previous
#include <cuda_runtime.h>
#include <cstdint>

// ---------------------------------------------------------------------------
// SwinIR-lite forward: conv3x3(3->60) -> 36 x [LN+WindowAttn+res, LN+MLP+res]
// -> conv3x3(60->12) + PixelShuffle(2).  B=2, H=W=128, C=60.
// R15: R12 + (a) weights pre-converted to padded tf32 slabs once per launch
//      (GEMM W-staging = pure uint4 copy), (b) residual prefetch into
//      registers before staging (epilogue RMW -> pure store).
// ---------------------------------------------------------------------------

constexpr int Bn   = 2;
constexpr int Hc   = 128;
constexpr int Wc   = 128;
constexpr int Cch  = 60;
constexpr int NHEADS = 3;
constexpr int NTOK = Bn * Hc * Wc;          // 32768 tokens
constexpr int NL   = 36;

// Scratch (device globals; no allocation allowed)
__device__ float g_feat[NTOK * Cch];        // 7.5 MB
__device__ float g_qkv [NTOK * 180];        // 22.5 MB
__device__ float g_attn[NTOK * Cch];        // 7.5 MB
__device__ float g_mlp [NTOK * 120];        // 15 MB

// Pre-converted tf32 weight slabs (padded to Kp x WST)
__device__ float g_wq[NL * 64 * 200];       // qkv  (K=60,N=180)
__device__ float g_wp[NL * 64 * 72];        // proj (K=60,N=60)
__device__ float g_w1[NL * 64 * 136];       // fc1  (K=60,N=120)
__device__ float g_w2[NL * 120 * 72];       // fc2  (K=120,N=60)

// ---- tf32 helpers ----------------------------------------------------------
__device__ __forceinline__ uint32_t f2tf(float v) {
    uint32_t r;
    asm("cvt.rna.tf32.f32 %0, %1;" : "=r"(r) : "f"(v));
    return r;
}
__device__ __forceinline__ void mma_tf32(float c[4],
    uint32_t a0, uint32_t a1, uint32_t a2, uint32_t a3,
    uint32_t b0, uint32_t b1)
{
    asm("mma.sync.aligned.m16n8k8.row.col.f32.tf32.tf32.f32 "
        "{%0,%1,%2,%3}, {%4,%5,%6,%7}, {%8,%9}, {%0,%1,%2,%3};"
        : "+f"(c[0]), "+f"(c[1]), "+f"(c[2]), "+f"(c[3])
        : "r"(a0), "r"(a1), "r"(a2), "r"(a3), "r"(b0), "r"(b1));
}

// ---------------------------------------------------------------------------
// Weight prep: convert + pad all layers of one family into tf32 slab.
// ---------------------------------------------------------------------------
template <int K, int N, int Kp, int WST, int FAM>
__global__ __launch_bounds__(256) void prep_w_k(const float* __restrict__ src)
{
    const int l = blockIdx.y;
    const int i = blockIdx.x * 256 + threadIdx.x;
    if (i >= Kp * WST) return;
    const int row = i / WST, col = i % WST;
    float v = 0.f;
    if (row < K && col < N) v = src[(size_t)l * K * N + row * N + col];
    float* dst = (FAM == 0) ? g_wq : (FAM == 1) ? g_wp
               : (FAM == 2) ? g_w1 : g_w2;
    dst[(size_t)l * (Kp * WST) + i] = __uint_as_float(f2tf(v));
}

// ---------------------------------------------------------------------------
// conv3x3 3->60, NCHW in -> NHWC (token-major) out
// ---------------------------------------------------------------------------
__global__ __launch_bounds__(256) void conv_in_k(
    const float* __restrict__ x, const float* __restrict__ w,
    const float* __restrict__ b)
{
    int idx = blockIdx.x * blockDim.x + threadIdx.x;
    if (idx >= NTOK * Cch) return;
    int co = idx % Cch;
    int p  = idx / Cch;
    int wx = p % Wc;
    int hy = (p / Wc) % Hc;
    int bb = p / (Wc * Hc);
    float acc = b[co];
#pragma unroll
    for (int ci = 0; ci < 3; ci++) {
#pragma unroll
        for (int kh = 0; kh < 3; kh++) {
            int hh = hy + kh - 1;
            if ((unsigned)hh >= (unsigned)Hc) continue;
#pragma unroll
            for (int kw = 0; kw < 3; kw++) {
                int ww2 = wx + kw - 1;
                if ((unsigned)ww2 >= (unsigned)Wc) continue;
                acc += x[((bb * 3 + ci) * Hc + hh) * Wc + ww2] *
                       w[((co * 3 + ci) * 3 + kh) * 3 + kw];
            }
        }
    }
    g_feat[idx] = acc;
}

// ---------------------------------------------------------------------------
// Unified tf32 tensor-core GEMM:  Y[T,N] = op(X[T,K]) @ W[K,N] + bias
//   LNF/SWISH as before; SRC: 0=feat 1=attn 2=mlp; DST: 0=qkv 1=mlp 2=feat+res
//   WFAM: 0=qkv 1=proj 2=fc1 3=fc2 (pre-converted slab)
// ---------------------------------------------------------------------------
template <int K, int Kp, int XST, int N, int Np, int WST, int NT, int KT,
          bool LNF, bool SWISH, int SRC, int DST, int WFAM, int MINB>
__global__ __launch_bounds__(256, MINB) void mma_gemm_k(
    const float* __restrict__ gamma, const float* __restrict__ beta,
    const float* __restrict__ bias, int l)
{
    extern __shared__ float sm[];
    float* ws   = sm;                    // Kp * WST   (tf32 bits)
    float* bs   = ws + Kp * WST;         // Np
    float* gs   = bs + Np;               // K
    float* bt   = gs + K;                // K
    float* mu_s = bt + K;                // 64
    float* rs_s = mu_s + 64;             // 64
    float* xs   = rs_s + 64;             // 64 * XST

    const int tid = threadIdx.x;
    const int T0  = blockIdx.x * 64;
    const float* src = (SRC == 0) ? g_feat : ((SRC == 1) ? g_attn : g_mlp);

    // mma coordinates (known immediately)
    const int wid = tid >> 5, lane = tid & 31;
    const int mt = wid >> 1, ng = wid & 1;
    const int g  = lane >> 2, tg = lane & 3;
    const int r0 = mt * 16 + g;
    const int gr0 = T0 + r0;
    const int gr1 = gr0 + 8;

    // residual prefetch (latency hidden behind staging + mma)
    float2 res0[NT], res1[NT];
    if (DST == 2) {
#pragma unroll
        for (int nt = 0; nt < NT; nt++) {
            const int col = (ng * NT + nt) * 8 + 2 * tg;
            if (col < N) {
                res0[nt] = *(const float2*)(g_feat + (size_t)gr0 * Cch + col);
                res1[nt] = *(const float2*)(g_feat + (size_t)gr1 * Cch + col);
            }
        }
    }

    // ---- stage W: pure uint4 copy of pre-converted slab ----
    {
        const float* wsrc = ((WFAM == 0) ? g_wq : (WFAM == 1) ? g_wp
                           : (WFAM == 2) ? g_w1 : g_w2)
                          + (size_t)l * (Kp * WST);
        const uint4* s4 = (const uint4*)wsrc;
        uint4*       d4 = (uint4*)ws;
        for (int i = tid; i < Kp * WST / 4; i += 256) d4[i] = s4[i];
    }
    for (int i = tid; i < Np; i += 256) bs[i] = (i < N) ? bias[i] : 0.f;
    if (LNF)
        for (int i = tid; i < K; i += 256) { gs[i] = gamma[i]; bt[i] = beta[i]; }

    // ---- stage X (raw if LN; else cvt immediately), zero-pad cols [K,Kp) ----
    {
        constexpr int KP4 = Kp / 4;
        for (int i = tid; i < 64 * KP4; i += 256) {
            int row = i / KP4, c4 = (i % KP4) * 4;
            float4 v = make_float4(0.f, 0.f, 0.f, 0.f);
            if (c4 < K) v = *(const float4*)(src + (size_t)(T0 + row) * K + c4);
            if (LNF) {
                *(float4*)(xs + row * XST + c4) = v;
            } else {
                uint4 o;
                o.x = f2tf(v.x); o.y = f2tf(v.y); o.z = f2tf(v.z); o.w = f2tf(v.w);
                *(uint4*)(xs + row * XST + c4) = o;
            }
        }
    }
    __syncthreads();

    if (LNF) {
        if (tid < 64) {
            float s = 0.f, s2 = 0.f;
            for (int k = 0; k < K; k++) {
                float v = xs[tid * XST + k];
                s += v; s2 += v * v;
            }
            float mu  = s * (1.0f / K);
            float var = s2 * (1.0f / K) - mu * mu;
            mu_s[tid] = mu;
            rs_s[tid] = rsqrtf(var + 1e-5f);
        }
        __syncthreads();
        for (int i = tid; i < 64 * K; i += 256) {
            int row = i / K, k = i % K;
            float v = xs[row * XST + k];
            v = (v - mu_s[row]) * rs_s[row] * gs[k] + bt[k];
            xs[row * XST + k] = __uint_as_float(f2tf(v));
        }
        __syncthreads();
    }

    float acc[NT][4];
#pragma unroll
    for (int nt = 0; nt < NT; nt++)
#pragma unroll
        for (int j = 0; j < 4; j++) acc[nt][j] = 0.f;

#pragma unroll
    for (int kt = 0; kt < KT; kt++) {
        const int k0 = kt * 8;
        uint32_t a0 = __float_as_uint(xs[r0 * XST + k0 + tg]);
        uint32_t a1 = __float_as_uint(xs[(r0 + 8) * XST + k0 + tg]);
        uint32_t a2 = __float_as_uint(xs[r0 * XST + k0 + tg + 4]);
        uint32_t a3 = __float_as_uint(xs[(r0 + 8) * XST + k0 + tg + 4]);
#pragma unroll
        for (int nt = 0; nt < NT; nt++) {
            const int nb = (ng * NT + nt) * 8 + g;
            uint32_t b0 = __float_as_uint(ws[(k0 + tg) * WST + nb]);
            uint32_t b1 = __float_as_uint(ws[(k0 + tg + 4) * WST + nb]);
            mma_tf32(acc[nt], a0, a1, a2, a3, b0, b1);
        }
    }

#pragma unroll
    for (int nt = 0; nt < NT; nt++) {
        const int col = (ng * NT + nt) * 8 + 2 * tg;
        if (col < N) {
            float v0 = acc[nt][0] + bs[col];
            float v1 = acc[nt][1] + bs[col + 1];
            float v2 = acc[nt][2] + bs[col];
            float v3 = acc[nt][3] + bs[col + 1];
            if (SWISH) {
                v0 /= 1.f + __expf(-v0);  v1 /= 1.f + __expf(-v1);
                v2 /= 1.f + __expf(-v2);  v3 /= 1.f + __expf(-v3);
            }
            if (DST == 0) {
                *(float2*)(g_qkv + (size_t)gr0 * N + col) = make_float2(v0, v1);
                *(float2*)(g_qkv + (size_t)gr1 * N + col) = make_float2(v2, v3);
            } else if (DST == 1) {
                *(float2*)(g_mlp + (size_t)gr0 * N + col) = make_float2(v0, v1);
                *(float2*)(g_mlp + (size_t)gr1 * N + col) = make_float2(v2, v3);
            } else {
                *(float2*)(g_feat + (size_t)gr0 * Cch + col) =
                    make_float2(res0[nt].x + v0, res0[nt].y + v1);
                *(float2*)(g_feat + (size_t)gr1 * Cch + col) =
                    make_float2(res1[nt].x + v2, res1[nt].y + v3);
            }
        }
    }
}

// ---------------------------------------------------------------------------
// Tensor-core window attention (unchanged from R12).
// ---------------------------------------------------------------------------
__global__ __launch_bounds__(256, 2) void attn_mma_k(int wh, int ww,
                                                     int sh, int sw,
                                                     int shifted)
{
    constexpr int KST = 28, VST = 24, PST = 36;
    extern __shared__ float asm_[];
    float* k_s   = asm_;                    // 256*28
    float* v_s   = k_s + 256 * KST;         // 256*24
    float* p_s   = v_s + 256 * VST;         // 256*36 (Q staging first)
    int*   tok_s = (int*)(p_s + 256 * PST); // 256
    int*   rg_s  = tok_s + 256;             // 256

    const int tid  = threadIdx.x;
    const int wid  = tid >> 5, lane = tid & 31;
    const int g    = lane >> 2, tg = lane & 3;
    const int head = blockIdx.y;
    const int win  = blockIdx.x;
    const int nW   = Wc / ww;
    const int perB = (Hc / wh) * nW;
    const int b    = win / perB;
    const int wr_  = win % perB;
    const int wy   = wr_ / nW, wx = wr_ % nW;

    // ---- stage one row per thread ----
    {
        const int n  = tid;
        const int iy = n / ww, ix = n % ww;
        const int hr = wy * wh + iy;
        const int wr = wx * ww + ix;
        int hs = hr + sh;  if (hs >= Hc) hs -= Hc;
        int ws2 = wr + sw; if (ws2 >= Wc) ws2 -= Wc;
        const int tok = (b * Hc + hs) * Wc + ws2;
        tok_s[n] = tok;
        if (shifted) {
            int rh = (hr < Hc - wh) ? 0 : ((hr < Hc - sh) ? 1 : 2);
            int rw = (wr < Wc - ww) ? 0 : ((wr < Wc - sw) ? 1 : 2);
            rg_s[n] = rh * 3 + rw;
        }
        const float4* qp = (const float4*)g_qkv;
        const size_t base4 = (size_t)tok * 45 + (size_t)head * 5;
        const float scale = 0.223606797749979f;   // 20^-0.5
#pragma unroll
        for (int i = 0; i < 5; i++) {
            float4 q = qp[base4 + i];
            float4 k = qp[base4 + 15 + i];
            float4 v = qp[base4 + 30 + i];
            uint4 qo, ko, vo;
            qo.x = f2tf(q.x * scale); qo.y = f2tf(q.y * scale);
            qo.z = f2tf(q.z * scale); qo.w = f2tf(q.w * scale);
            ko.x = f2tf(k.x); ko.y = f2tf(k.y); ko.z = f2tf(k.z); ko.w = f2tf(k.w);
            vo.x = f2tf(v.x); vo.y = f2tf(v.y); vo.z = f2tf(v.z); vo.w = f2tf(v.w);
            p_s[n * KST + 4 * i + 0] = __uint_as_float(qo.x);
            p_s[n * KST + 4 * i + 1] = __uint_as_float(qo.y);
            p_s[n * KST + 4 * i + 2] = __uint_as_float(qo.z);
            p_s[n * KST + 4 * i + 3] = __uint_as_float(qo.w);
            k_s[n * KST + 4 * i + 0] = __uint_as_float(ko.x);
            k_s[n * KST + 4 * i + 1] = __uint_as_float(ko.y);
            k_s[n * KST + 4 * i + 2] = __uint_as_float(ko.z);
            k_s[n * KST + 4 * i + 3] = __uint_as_float(ko.w);
            v_s[n * VST + 4 * i + 0] = __uint_as_float(vo.x);
            v_s[n * VST + 4 * i + 1] = __uint_as_float(vo.y);
            v_s[n * VST + 4 * i + 2] = __uint_as_float(vo.z);
            v_s[n * VST + 4 * i + 3] = __uint_as_float(vo.w);
        }
#pragma unroll
        for (int c = 20; c < 24; c++) {     // zero pads (kt=2 reads cols 20..23)
            p_s[n * KST + c] = 0.f;
            k_s[n * KST + c] = 0.f;
            v_s[n * VST + c] = 0.f;
        }
    }
    __syncthreads();

    // ---- preload Q fragments (rows fixed per warp) ----
    const int wr0 = wid * 32;
    uint32_t qf[2][3][4];
    int rgA[2], rgB[2];
#pragma unroll
    for (int mt = 0; mt < 2; mt++) {
        const int r0 = wr0 + mt * 16 + g;
#pragma unroll
        for (int kt = 0; kt < 3; kt++) {
            const int c = kt * 8 + tg;
            qf[mt][kt][0] = __float_as_uint(p_s[r0 * KST + c]);
            qf[mt][kt][1] = __float_as_uint(p_s[(r0 + 8) * KST + c]);
            qf[mt][kt][2] = __float_as_uint(p_s[r0 * KST + c + 4]);
            qf[mt][kt][3] = __float_as_uint(p_s[(r0 + 8) * KST + c + 4]);
        }
        if (shifted) { rgA[mt] = rg_s[r0]; rgB[mt] = rg_s[r0 + 8]; }
    }
    __syncthreads();   // Q reads done; p_s now reused for P chunks

    float oacc[2][3][4];
#pragma unroll
    for (int mt = 0; mt < 2; mt++)
#pragma unroll
        for (int nt = 0; nt < 3; nt++)
#pragma unroll
            for (int j = 0; j < 4; j++) oacc[mt][nt][j] = 0.f;
    float dsum[2][2] = {{0.f, 0.f}, {0.f, 0.f}};

    for (int c = 0; c < 8; c++) {           // key chunks of 32
        const int kb = c * 32;
#pragma unroll
        for (int mt = 0; mt < 2; mt++) {
            float sacc[4][4];
#pragma unroll
            for (int nt = 0; nt < 4; nt++)
#pragma unroll
                for (int j = 0; j < 4; j++) sacc[nt][j] = 0.f;
#pragma unroll
            for (int kt = 0; kt < 3; kt++) {
                const int k0 = kt * 8;
#pragma unroll
                for (int nt = 0; nt < 4; nt++) {
                    const int nb = kb + nt * 8 + g;
                    uint32_t b0 = __float_as_uint(k_s[nb * KST + k0 + tg]);
                    uint32_t b1 = __float_as_uint(k_s[nb * KST + k0 + tg + 4]);
                    mma_tf32(sacc[nt], qf[mt][kt][0], qf[mt][kt][1],
                             qf[mt][kt][2], qf[mt][kt][3], b0, b1);
                }
            }
            const int r0 = wr0 + mt * 16 + g;
#pragma unroll
            for (int nt = 0; nt < 4; nt++) {
                const int col0 = kb + nt * 8 + 2 * tg;
                float s0 = sacc[nt][0], s1 = sacc[nt][1];
                float s2 = sacc[nt][2], s3 = sacc[nt][3];
                if (shifted) {
                    int rc0 = rg_s[col0], rc1 = rg_s[col0 + 1];
                    if (rc0 != rgA[mt]) s0 -= 100.f;
                    if (rc1 != rgA[mt]) s1 -= 100.f;
                    if (rc0 != rgB[mt]) s2 -= 100.f;
                    if (rc1 != rgB[mt]) s3 -= 100.f;
                }
                float p0 = __expf(s0), p1 = __expf(s1);
                float p2 = __expf(s2), p3 = __expf(s3);
                dsum[mt][0] += p0 + p1;
                dsum[mt][1] += p2 + p3;
                uint2 u0 = make_uint2(f2tf(p0), f2tf(p1));
                uint2 u1 = make_uint2(f2tf(p2), f2tf(p3));
                *(uint2*)(p_s + r0 * PST + nt * 8 + 2 * tg)       = u0;
                *(uint2*)(p_s + (r0 + 8) * PST + nt * 8 + 2 * tg) = u1;
            }
        }
        __syncwarp();
#pragma unroll
        for (int kt2 = 0; kt2 < 4; kt2++) {
            const int kr = kb + kt2 * 8;
#pragma unroll
            for (int mt = 0; mt < 2; mt++) {
                const int r0 = wr0 + mt * 16 + g;
                uint32_t a0 = __float_as_uint(p_s[r0 * PST + kt2 * 8 + tg]);
                uint32_t a1 = __float_as_uint(p_s[(r0 + 8) * PST + kt2 * 8 + tg]);
                uint32_t a2 = __float_as_uint(p_s[r0 * PST + kt2 * 8 + tg + 4]);
                uint32_t a3 = __float_as_uint(p_s[(r0 + 8) * PST + kt2 * 8 + tg + 4]);
#pragma unroll
                for (int nt = 0; nt < 3; nt++) {
                    const int nb = nt * 8 + g;
                    uint32_t b0 = __float_as_uint(v_s[(kr + tg) * VST + nb]);
                    uint32_t b1 = __float_as_uint(v_s[(kr + tg + 4) * VST + nb]);
                    mma_tf32(oacc[mt][nt], a0, a1, a2, a3, b0, b1);
                }
            }
        }
        __syncwarp();
    }

    // ---- denominators: reduce across quad (lanes share rows) ----
    float inv[2][2];
#pragma unroll
    for (int mt = 0; mt < 2; mt++)
#pragma unroll
        for (int j = 0; j < 2; j++) {
            float d = dsum[mt][j];
            d += __shfl_xor_sync(0xFFFFFFFFu, d, 1);
            d += __shfl_xor_sync(0xFFFFFFFFu, d, 2);
            inv[mt][j] = 1.f / d;
        }

    // ---- epilogue ----
#pragma unroll
    for (int mt = 0; mt < 2; mt++) {
        const int r0 = wr0 + mt * 16 + g;
        const int tok0 = tok_s[r0];
        const int tok1 = tok_s[r0 + 8];
#pragma unroll
        for (int nt = 0; nt < 3; nt++) {
            const int col = nt * 8 + 2 * tg;
            if (col < 20) {
                float2 w0 = make_float2(oacc[mt][nt][0] * inv[mt][0],
                                        oacc[mt][nt][1] * inv[mt][0]);
                float2 w1 = make_float2(oacc[mt][nt][2] * inv[mt][1],
                                        oacc[mt][nt][3] * inv[mt][1]);
                *(float2*)(g_attn + (size_t)tok0 * Cch + head * 20 + col) = w0;
                *(float2*)(g_attn + (size_t)tok1 * Cch + head * 20 + col) = w1;
            }
        }
    }
}

// ---------------------------------------------------------------------------
// conv3x3 60->12 + PixelShuffle(2) fused.
// ---------------------------------------------------------------------------
__global__ __launch_bounds__(256) void conv_out_k(
    const float* __restrict__ lw, const float* __restrict__ lb,
    float* __restrict__ out)
{
    const int TOT = Bn * 3 * 256 * 256;
    int idx = blockIdx.x * blockDim.x + threadIdx.x;
    if (idx >= TOT) return;
    int w2 = idx & 255;
    int h2 = (idx >> 8) & 255;
    int c  = (idx >> 16) % 3;
    int bb = idx / (3 * 65536);
    int co = c * 4 + (h2 & 1) * 2 + (w2 & 1);
    int h  = h2 >> 1, w = w2 >> 1;
    float acc = lb[co];
#pragma unroll
    for (int kh = 0; kh < 3; kh++) {
        int hh = h + kh - 1;
        if ((unsigned)hh >= (unsigned)Hc) continue;
#pragma unroll
        for (int kw = 0; kw < 3; kw++) {
            int ww2 = w + kw - 1;
            if ((unsigned)ww2 >= (unsigned)Wc) continue;
            const float* fp = g_feat + ((size_t)(bb * Hc + hh) * Wc + ww2) * Cch;
            const float* wp = lw + co * (Cch * 9) + kh * 3 + kw;
#pragma unroll
            for (int ci = 0; ci < Cch; ci++)
                acc = fmaf(fp[ci], wp[ci * 9], acc);
        }
    }
    out[idx] = acc;
}

// ---------------------------------------------------------------------------
// Launch
// ---------------------------------------------------------------------------

constexpr int smf(int K, int Kp, int XST, int Np, int WST) {
    return Kp * WST + Np + 2 * K + 128 + 64 * XST;
}

extern "C" void kernel_launch(void* const* d_in, const int* in_sizes, int n_in,
                              void* d_out, int out_size)
{
    (void)in_sizes; (void)n_in; (void)out_size;
    const float* x      = (const float*)d_in[0];
    const float* conv_w = (const float*)d_in[1];
    const float* conv_b = (const float*)d_in[2];
    const float* ln1_g  = (const float*)d_in[3];
    const float* ln1_b  = (const float*)d_in[4];
    const float* qkv_w  = (const float*)d_in[5];
    const float* qkv_b  = (const float*)d_in[6];
    const float* proj_w = (const float*)d_in[7];
    const float* proj_b = (const float*)d_in[8];
    const float* ln2_g  = (const float*)d_in[9];
    const float* ln2_b  = (const float*)d_in[10];
    const float* fc1_w  = (const float*)d_in[11];
    const float* fc1_b  = (const float*)d_in[12];
    const float* fc2_w  = (const float*)d_in[13];
    const float* fc2_b  = (const float*)d_in[14];
    const float* last_w = (const float*)d_in[15];
    const float* last_b = (const float*)d_in[16];
    float* out = (float*)d_out;

    constexpr int SM_QKV  = smf(60, 64, 68, 192, 200) * 4;
    constexpr int SM_FC1  = smf(60, 64, 68, 128, 136) * 4;
    constexpr int SM_PROJ = smf(60, 64, 68, 64, 72) * 4;
    constexpr int SM_FC2  = smf(120, 120, 124, 64, 72) * 4;
    constexpr int SM_ATTN = (256 * 28 + 256 * 24 + 256 * 36 + 512) * 4;  // 92160

    cudaFuncSetAttribute(
        mma_gemm_k<60, 64, 68, 180, 192, 200, 12, 8, true, false, 0, 0, 0, 3>,
        cudaFuncAttributeMaxDynamicSharedMemorySize, SM_QKV);
    cudaFuncSetAttribute(
        mma_gemm_k<60, 64, 68, 120, 128, 136, 8, 8, true, true, 0, 1, 2, 4>,
        cudaFuncAttributeMaxDynamicSharedMemorySize, SM_FC1);
    cudaFuncSetAttribute(
        mma_gemm_k<60, 64, 68, 60, 64, 72, 4, 8, false, false, 1, 2, 1, 4>,
        cudaFuncAttributeMaxDynamicSharedMemorySize, SM_PROJ);
    cudaFuncSetAttribute(
        mma_gemm_k<120, 120, 124, 60, 64, 72, 4, 15, false, false, 2, 2, 3, 3>,
        cudaFuncAttributeMaxDynamicSharedMemorySize, SM_FC2);
    cudaFuncSetAttribute(attn_mma_k,
        cudaFuncAttributeMaxDynamicSharedMemorySize, SM_ATTN);

    // one-time weight prep (part of the captured graph; ~µs)
    prep_w_k<60, 180, 64, 200, 0><<<dim3(50, NL), 256>>>(qkv_w);
    prep_w_k<60, 60, 64, 72, 1><<<dim3(18, NL), 256>>>(proj_w);
    prep_w_k<60, 120, 64, 136, 2><<<dim3(34, NL), 256>>>(fc1_w);
    prep_w_k<120, 60, 120, 72, 3><<<dim3(34, NL), 256>>>(fc2_w);

    conv_in_k<<<(NTOK * Cch + 255) / 256, 256>>>(x, conv_w, conv_b);

    const int GG = NTOK / 64;   // 512

    for (int l = 0; l < NL; l++) {
        int i  = l % 6;
        int wi = i % 2;
        int wh = wi ? 8 : 32;
        int ww = wi ? 32 : 8;
        int shifted = (i % 4) >= 2;
        int sh = shifted ? (wi ? 4 : 16) : 0;
        int sw = shifted ? (wi ? 16 : 4) : 0;

        mma_gemm_k<60, 64, 68, 180, 192, 200, 12, 8, true, false, 0, 0, 0, 3>
            <<<GG, 256, SM_QKV>>>(ln1_g + l * 60, ln1_b + l * 60,
                                  qkv_b + l * 180, l);

        attn_mma_k<<<dim3(Bn * 64, NHEADS), 256, SM_ATTN>>>(wh, ww, sh, sw,
                                                            shifted);

        mma_gemm_k<60, 64, 68, 60, 64, 72, 4, 8, false, false, 1, 2, 1, 4>
            <<<GG, 256, SM_PROJ>>>(nullptr, nullptr, proj_b + l * 60, l);

        mma_gemm_k<60, 64, 68, 120, 128, 136, 8, 8, true, true, 0, 1, 2, 4>
            <<<GG, 256, SM_FC1>>>(ln2_g + l * 60, ln2_b + l * 60,
                                  fc1_b + l * 120, l);

        mma_gemm_k<120, 120, 124, 60, 64, 72, 4, 15, false, false, 2, 2, 3, 3>
            <<<GG, 256, SM_FC2>>>(nullptr, nullptr, fc2_b + l * 60, l);
    }

    conv_out_k<<<(Bn * 3 * 256 * 256 + 255) / 256, 256>>>(last_w, last_b, out);
}

// round 16
// speedup vs baseline: 1.9555x; 1.0004x over previous
#include <cuda_runtime.h>
#include <cstdint>

// ---------------------------------------------------------------------------
// SwinIR-lite forward.  B=2, H=W=128, C=60.
// R16: layer = qkv(LN1) -> attn -> FUSED[proj+res+LN2+fc1+swish+fc2+res].
//      The fused kernel keeps the 32-token feat tile in smem across phases,
//      reuses one W region (Wp->W1->W2), never touches g_mlp, writes g_feat
//      once.  tf32 mma everywhere; weights pre-converted (R15).
// ---------------------------------------------------------------------------

constexpr int Bn   = 2;
constexpr int Hc   = 128;
constexpr int Wc   = 128;
constexpr int Cch  = 60;
constexpr int NHEADS = 3;
constexpr int NTOK = Bn * Hc * Wc;          // 32768 tokens
constexpr int NL   = 36;

// Scratch (device globals; no allocation allowed)
__device__ float g_feat[NTOK * Cch];        // 7.5 MB
__device__ float g_qkv [NTOK * 180];        // 22.5 MB
__device__ float g_attn[NTOK * Cch];        // 7.5 MB

// Pre-converted tf32 weight slabs (padded to Kp x WST)
__device__ float g_wq[NL * 64 * 200];       // qkv  (K=60,N=180)
__device__ float g_wp[NL * 64 * 72];        // proj (K=60,N=60)
__device__ float g_w1[NL * 64 * 136];       // fc1  (K=60,N=120)
__device__ float g_w2[NL * 120 * 72];       // fc2  (K=120,N=60)

// ---- tf32 helpers ----------------------------------------------------------
__device__ __forceinline__ uint32_t f2tf(float v) {
    uint32_t r;
    asm("cvt.rna.tf32.f32 %0, %1;" : "=r"(r) : "f"(v));
    return r;
}
__device__ __forceinline__ void mma_tf32(float c[4],
    uint32_t a0, uint32_t a1, uint32_t a2, uint32_t a3,
    uint32_t b0, uint32_t b1)
{
    asm("mma.sync.aligned.m16n8k8.row.col.f32.tf32.tf32.f32 "
        "{%0,%1,%2,%3}, {%4,%5,%6,%7}, {%8,%9}, {%0,%1,%2,%3};"
        : "+f"(c[0]), "+f"(c[1]), "+f"(c[2]), "+f"(c[3])
        : "r"(a0), "r"(a1), "r"(a2), "r"(a3), "r"(b0), "r"(b1));
}

// ---------------------------------------------------------------------------
// Weight prep: convert + pad all layers of one family into tf32 slab.
// ---------------------------------------------------------------------------
template <int K, int N, int Kp, int WST, int FAM>
__global__ __launch_bounds__(256) void prep_w_k(const float* __restrict__ src)
{
    const int l = blockIdx.y;
    const int i = blockIdx.x * 256 + threadIdx.x;
    if (i >= Kp * WST) return;
    const int row = i / WST, col = i % WST;
    float v = 0.f;
    if (row < K && col < N) v = src[(size_t)l * K * N + row * N + col];
    float* dst = (FAM == 0) ? g_wq : (FAM == 1) ? g_wp
               : (FAM == 2) ? g_w1 : g_w2;
    dst[(size_t)l * (Kp * WST) + i] = __uint_as_float(f2tf(v));
}

// ---------------------------------------------------------------------------
// conv3x3 3->60, NCHW in -> NHWC (token-major) out
// ---------------------------------------------------------------------------
__global__ __launch_bounds__(256) void conv_in_k(
    const float* __restrict__ x, const float* __restrict__ w,
    const float* __restrict__ b)
{
    int idx = blockIdx.x * blockDim.x + threadIdx.x;
    if (idx >= NTOK * Cch) return;
    int co = idx % Cch;
    int p  = idx / Cch;
    int wx = p % Wc;
    int hy = (p / Wc) % Hc;
    int bb = p / (Wc * Hc);
    float acc = b[co];
#pragma unroll
    for (int ci = 0; ci < 3; ci++) {
#pragma unroll
        for (int kh = 0; kh < 3; kh++) {
            int hh = hy + kh - 1;
            if ((unsigned)hh >= (unsigned)Hc) continue;
#pragma unroll
            for (int kw = 0; kw < 3; kw++) {
                int ww2 = wx + kw - 1;
                if ((unsigned)ww2 >= (unsigned)Wc) continue;
                acc += x[((bb * 3 + ci) * Hc + hh) * Wc + ww2] *
                       w[((co * 3 + ci) * 3 + kh) * 3 + kw];
            }
        }
    }
    g_feat[idx] = acc;
}

// ---------------------------------------------------------------------------
// qkv GEMM (LN1 + X@Wq + bias -> g_qkv), unchanged from R15.
// TM=64 tokens, 256 thr, grid 512.
// ---------------------------------------------------------------------------
template <int MINB>
__global__ __launch_bounds__(256, MINB) void qkv_gemm_k(
    const float* __restrict__ gamma, const float* __restrict__ beta,
    const float* __restrict__ bias, int l)
{
    constexpr int K = 60, Kp = 64, XST = 68, N = 180, Np = 192, WST = 200;
    constexpr int NT = 12, KT = 8;
    extern __shared__ float sm[];
    float* ws   = sm;                    // Kp * WST
    float* bs   = ws + Kp * WST;         // Np
    float* gs   = bs + Np;               // K
    float* bt   = gs + K;                // K
    float* mu_s = bt + K;                // 64
    float* rs_s = mu_s + 64;             // 64
    float* xs   = rs_s + 64;             // 64 * XST

    const int tid = threadIdx.x;
    const int T0  = blockIdx.x * 64;

    {
        const uint4* s4 = (const uint4*)(g_wq + (size_t)l * (Kp * WST));
        uint4*       d4 = (uint4*)ws;
        for (int i = tid; i < Kp * WST / 4; i += 256) d4[i] = s4[i];
    }
    for (int i = tid; i < Np; i += 256) bs[i] = (i < N) ? bias[i] : 0.f;
    for (int i = tid; i < K; i += 256) { gs[i] = gamma[i]; bt[i] = beta[i]; }

    {
        constexpr int KP4 = Kp / 4;
        for (int i = tid; i < 64 * KP4; i += 256) {
            int row = i / KP4, c4 = (i % KP4) * 4;
            float4 v = make_float4(0.f, 0.f, 0.f, 0.f);
            if (c4 < K) v = *(const float4*)(g_feat + (size_t)(T0 + row) * K + c4);
            *(float4*)(xs + row * XST + c4) = v;
        }
    }
    __syncthreads();

    if (tid < 64) {
        float s = 0.f, s2 = 0.f;
        for (int k = 0; k < K; k++) {
            float v = xs[tid * XST + k];
            s += v; s2 += v * v;
        }
        float mu  = s * (1.0f / K);
        float var = s2 * (1.0f / K) - mu * mu;
        mu_s[tid] = mu;
        rs_s[tid] = rsqrtf(var + 1e-5f);
    }
    __syncthreads();
    for (int i = tid; i < 64 * K; i += 256) {
        int row = i / K, k = i % K;
        float v = xs[row * XST + k];
        v = (v - mu_s[row]) * rs_s[row] * gs[k] + bt[k];
        xs[row * XST + k] = __uint_as_float(f2tf(v));
    }
    __syncthreads();

    const int wid = tid >> 5, lane = tid & 31;
    const int mt = wid >> 1, ng = wid & 1;
    const int g  = lane >> 2, tg = lane & 3;
    const int r0 = mt * 16 + g;

    float acc[NT][4];
#pragma unroll
    for (int nt = 0; nt < NT; nt++)
#pragma unroll
        for (int j = 0; j < 4; j++) acc[nt][j] = 0.f;

#pragma unroll
    for (int kt = 0; kt < KT; kt++) {
        const int k0 = kt * 8;
        uint32_t a0 = __float_as_uint(xs[r0 * XST + k0 + tg]);
        uint32_t a1 = __float_as_uint(xs[(r0 + 8) * XST + k0 + tg]);
        uint32_t a2 = __float_as_uint(xs[r0 * XST + k0 + tg + 4]);
        uint32_t a3 = __float_as_uint(xs[(r0 + 8) * XST + k0 + tg + 4]);
#pragma unroll
        for (int nt = 0; nt < NT; nt++) {
            const int nb = (ng * NT + nt) * 8 + g;
            uint32_t b0 = __float_as_uint(ws[(k0 + tg) * WST + nb]);
            uint32_t b1 = __float_as_uint(ws[(k0 + tg + 4) * WST + nb]);
            mma_tf32(acc[nt], a0, a1, a2, a3, b0, b1);
        }
    }

    const int gr0 = T0 + mt * 16 + g;
    const int gr1 = gr0 + 8;
#pragma unroll
    for (int nt = 0; nt < NT; nt++) {
        const int col = (ng * NT + nt) * 8 + 2 * tg;
        if (col < N) {
            *(float2*)(g_qkv + (size_t)gr0 * N + col) =
                make_float2(acc[nt][0] + bs[col], acc[nt][1] + bs[col + 1]);
            *(float2*)(g_qkv + (size_t)gr1 * N + col) =
                make_float2(acc[nt][2] + bs[col], acc[nt][3] + bs[col + 1]);
        }
    }
}

// ---------------------------------------------------------------------------
// FUSED proj + residual + LN2 + fc1 + swish + fc2 + residual.
// 32 tokens/block, 256 thr (8 warps = 2 mtiles x 4 nslabs), grid 1024.
// smem: ws(8704 reused Wp->W1->W2) bp(64) b1(128) b2(64) gs(60) bt(60)
//       mu(32) rs(32) xs(32x68) fs(32x68 feat fp32) hs(32x124 h tf32)
//       = 17464 floats = 69856 B -> 3 blocks/SM.
// ---------------------------------------------------------------------------
__global__ __launch_bounds__(256, 3) void fused_pm_k(
    const float* __restrict__ gamma, const float* __restrict__ beta,
    const float* __restrict__ proj_b, const float* __restrict__ fc1_b,
    const float* __restrict__ fc2_b, int l)
{
    extern __shared__ float sm[];
    float* ws = sm;                 // 8704
    float* bp = ws + 8704;          // 64
    float* b1 = bp + 64;            // 128
    float* b2 = b1 + 128;           // 64
    float* gs = b2 + 64;            // 60
    float* bt = gs + 60;            // 60
    float* mu_s = bt + 60;          // 32
    float* rs_s = mu_s + 32;        // 32
    float* xs = rs_s + 32;          // 32*68 = 2176
    float* fs = xs + 2176;          // 32*68 = 2176
    float* hs = fs + 2176;          // 32*124 = 3968

    const int tid = threadIdx.x;
    const int T0  = blockIdx.x * 32;
    const int wid = tid >> 5, lane = tid & 31;
    const int mt = wid >> 2, ng = wid & 3;      // 2 mtiles x 4 nslabs
    const int g  = lane >> 2, tg = lane & 3;
    const int r0 = mt * 16 + g;                 // row in tile (and +8)

    // ---- phase 1: stage Wp, biases, LN params, x (attn, tf32), feat tile ----
    {
        const uint4* s4 = (const uint4*)(g_wp + (size_t)l * 4608);
        uint4*       d4 = (uint4*)ws;
        for (int i = tid; i < 4608 / 4; i += 256) d4[i] = s4[i];
    }
    for (int i = tid; i < 64; i += 256)  bp[i] = (i < 60) ? proj_b[i] : 0.f;
    for (int i = tid; i < 128; i += 256) b1[i] = (i < 120) ? fc1_b[i] : 0.f;
    for (int i = tid; i < 64; i += 256)  b2[i] = (i < 60) ? fc2_b[i] : 0.f;
    for (int i = tid; i < 60; i += 256) { gs[i] = gamma[i]; bt[i] = beta[i]; }
    for (int i = tid; i < 32 * 16; i += 256) {          // xs: Kp/4 = 16
        int row = i >> 4, c4 = (i & 15) * 4;
        float4 v = make_float4(0.f, 0.f, 0.f, 0.f);
        if (c4 < 60) v = *(const float4*)(g_attn + (size_t)(T0 + row) * 60 + c4);
        uint4 o;
        o.x = f2tf(v.x); o.y = f2tf(v.y); o.z = f2tf(v.z); o.w = f2tf(v.w);
        *(uint4*)(xs + row * 68 + c4) = o;
    }
    for (int i = tid; i < 32 * 17; i += 256) {          // fs: 68/4 = 17
        int row = i / 17, c4 = (i % 17) * 4;
        float4 v = make_float4(0.f, 0.f, 0.f, 0.f);
        if (c4 < 60) v = *(const float4*)(g_feat + (size_t)(T0 + row) * 60 + c4);
        *(float4*)(fs + row * 68 + c4) = v;
    }
    __syncthreads();

    // ---- proj mma (K=60/Kp=64, N=60/Np=64, NT=2) ----
    {
        float acc[2][4];
#pragma unroll
        for (int nt = 0; nt < 2; nt++)
#pragma unroll
            for (int j = 0; j < 4; j++) acc[nt][j] = 0.f;
#pragma unroll
        for (int kt = 0; kt < 8; kt++) {
            const int k0 = kt * 8;
            uint32_t a0 = __float_as_uint(xs[r0 * 68 + k0 + tg]);
            uint32_t a1 = __float_as_uint(xs[(r0 + 8) * 68 + k0 + tg]);
            uint32_t a2 = __float_as_uint(xs[r0 * 68 + k0 + tg + 4]);
            uint32_t a3 = __float_as_uint(xs[(r0 + 8) * 68 + k0 + tg + 4]);
#pragma unroll
            for (int nt = 0; nt < 2; nt++) {
                const int nb = (ng * 2 + nt) * 8 + g;
                uint32_t b0 = __float_as_uint(ws[(k0 + tg) * 72 + nb]);
                uint32_t b1r = __float_as_uint(ws[(k0 + tg + 4) * 72 + nb]);
                mma_tf32(acc[nt], a0, a1, a2, a3, b0, b1r);
            }
        }
        // epilogue: + bias + residual(fs) -> fs (feat tile updated in smem)
#pragma unroll
        for (int nt = 0; nt < 2; nt++) {
            const int col = (ng * 2 + nt) * 8 + 2 * tg;
            if (col < 60) {
                float2 f0 = *(float2*)(fs + r0 * 68 + col);
                float2 f1 = *(float2*)(fs + (r0 + 8) * 68 + col);
                f0.x += acc[nt][0] + bp[col];
                f0.y += acc[nt][1] + bp[col + 1];
                f1.x += acc[nt][2] + bp[col];
                f1.y += acc[nt][3] + bp[col + 1];
                *(float2*)(fs + r0 * 68 + col) = f0;
                *(float2*)(fs + (r0 + 8) * 68 + col) = f1;
            }
        }
    }
    __syncthreads();

    // ---- stage W1 (overwrites Wp) + LN2 stats ----
    {
        const uint4* s4 = (const uint4*)(g_w1 + (size_t)l * 8704);
        uint4*       d4 = (uint4*)ws;
        for (int i = tid; i < 8704 / 4; i += 256) d4[i] = s4[i];
    }
    if (tid < 32) {
        float s = 0.f, s2 = 0.f;
        for (int k = 0; k < 60; k++) {
            float v = fs[tid * 68 + k];
            s += v; s2 += v * v;
        }
        float mu  = s * (1.0f / 60.f);
        float var = s2 * (1.0f / 60.f) - mu * mu;
        mu_s[tid] = mu;
        rs_s[tid] = rsqrtf(var + 1e-5f);
    }
    __syncthreads();

    // ---- normalize into xs (tf32); cols 60..63 already zero ----
    for (int i = tid; i < 32 * 60; i += 256) {
        int row = i / 60, k = i % 60;
        float v = (fs[row * 68 + k] - mu_s[row]) * rs_s[row] * gs[k] + bt[k];
        xs[row * 68 + k] = __uint_as_float(f2tf(v));
    }
    __syncthreads();

    // ---- fc1 mma (K=60/Kp=64, N=120/Np=128, NT=4) + swish -> hs ----
    {
        float acc[4][4];
#pragma unroll
        for (int nt = 0; nt < 4; nt++)
#pragma unroll
            for (int j = 0; j < 4; j++) acc[nt][j] = 0.f;
#pragma unroll
        for (int kt = 0; kt < 8; kt++) {
            const int k0 = kt * 8;
            uint32_t a0 = __float_as_uint(xs[r0 * 68 + k0 + tg]);
            uint32_t a1 = __float_as_uint(xs[(r0 + 8) * 68 + k0 + tg]);
            uint32_t a2 = __float_as_uint(xs[r0 * 68 + k0 + tg + 4]);
            uint32_t a3 = __float_as_uint(xs[(r0 + 8) * 68 + k0 + tg + 4]);
#pragma unroll
            for (int nt = 0; nt < 4; nt++) {
                const int nb = (ng * 4 + nt) * 8 + g;
                uint32_t b0 = __float_as_uint(ws[(k0 + tg) * 136 + nb]);
                uint32_t b1r = __float_as_uint(ws[(k0 + tg + 4) * 136 + nb]);
                mma_tf32(acc[nt], a0, a1, a2, a3, b0, b1r);
            }
        }
#pragma unroll
        for (int nt = 0; nt < 4; nt++) {
            const int col = (ng * 4 + nt) * 8 + 2 * tg;
            if (col < 120) {
                float v0 = acc[nt][0] + b1[col];
                float v1 = acc[nt][1] + b1[col + 1];
                float v2 = acc[nt][2] + b1[col];
                float v3 = acc[nt][3] + b1[col + 1];
                v0 /= 1.f + __expf(-v0);  v1 /= 1.f + __expf(-v1);
                v2 /= 1.f + __expf(-v2);  v3 /= 1.f + __expf(-v3);
                *(uint2*)(hs + r0 * 124 + col) =
                    make_uint2(f2tf(v0), f2tf(v1));
                *(uint2*)(hs + (r0 + 8) * 124 + col) =
                    make_uint2(f2tf(v2), f2tf(v3));
            }
        }
    }
    __syncthreads();

    // ---- stage W2 (overwrites W1) ----
    {
        const uint4* s4 = (const uint4*)(g_w2 + (size_t)l * 8640);
        uint4*       d4 = (uint4*)ws;
        for (int i = tid; i < 8640 / 4; i += 256) d4[i] = s4[i];
    }
    __syncthreads();

    // ---- fc2 mma (K=120, N=60/Np=64, NT=2) + residual(fs) -> g_feat ----
    {
        float acc[2][4];
#pragma unroll
        for (int nt = 0; nt < 2; nt++)
#pragma unroll
            for (int j = 0; j < 4; j++) acc[nt][j] = 0.f;
#pragma unroll
        for (int kt = 0; kt < 15; kt++) {
            const int k0 = kt * 8;
            uint32_t a0 = __float_as_uint(hs[r0 * 124 + k0 + tg]);
            uint32_t a1 = __float_as_uint(hs[(r0 + 8) * 124 + k0 + tg]);
            uint32_t a2 = __float_as_uint(hs[r0 * 124 + k0 + tg + 4]);
            uint32_t a3 = __float_as_uint(hs[(r0 + 8) * 124 + k0 + tg + 4]);
#pragma unroll
            for (int nt = 0; nt < 2; nt++) {
                const int nb = (ng * 2 + nt) * 8 + g;
                uint32_t b0 = __float_as_uint(ws[(k0 + tg) * 72 + nb]);
                uint32_t b1r = __float_as_uint(ws[(k0 + tg + 4) * 72 + nb]);
                mma_tf32(acc[nt], a0, a1, a2, a3, b0, b1r);
            }
        }
        const int gr0 = T0 + r0;
        const int gr1 = gr0 + 8;
#pragma unroll
        for (int nt = 0; nt < 2; nt++) {
            const int col = (ng * 2 + nt) * 8 + 2 * tg;
            if (col < 60) {
                float2 f0 = *(float2*)(fs + r0 * 68 + col);
                float2 f1 = *(float2*)(fs + (r0 + 8) * 68 + col);
                *(float2*)(g_feat + (size_t)gr0 * 60 + col) =
                    make_float2(f0.x + acc[nt][0] + b2[col],
                                f0.y + acc[nt][1] + b2[col + 1]);
                *(float2*)(g_feat + (size_t)gr1 * 60 + col) =
                    make_float2(f1.x + acc[nt][2] + b2[col],
                                f1.y + acc[nt][3] + b2[col + 1]);
            }
        }
    }
}

// ---------------------------------------------------------------------------
// Tensor-core window attention (unchanged from R12).
// ---------------------------------------------------------------------------
__global__ __launch_bounds__(256, 2) void attn_mma_k(int wh, int ww,
                                                     int sh, int sw,
                                                     int shifted)
{
    constexpr int KST = 28, VST = 24, PST = 36;
    extern __shared__ float asm_[];
    float* k_s   = asm_;                    // 256*28
    float* v_s   = k_s + 256 * KST;         // 256*24
    float* p_s   = v_s + 256 * VST;         // 256*36 (Q staging first)
    int*   tok_s = (int*)(p_s + 256 * PST); // 256
    int*   rg_s  = tok_s + 256;             // 256

    const int tid  = threadIdx.x;
    const int wid  = tid >> 5, lane = tid & 31;
    const int g    = lane >> 2, tg = lane & 3;
    const int head = blockIdx.y;
    const int win  = blockIdx.x;
    const int nW   = Wc / ww;
    const int perB = (Hc / wh) * nW;
    const int b    = win / perB;
    const int wr_  = win % perB;
    const int wy   = wr_ / nW, wx = wr_ % nW;

    {
        const int n  = tid;
        const int iy = n / ww, ix = n % ww;
        const int hr = wy * wh + iy;
        const int wr = wx * ww + ix;
        int hs = hr + sh;  if (hs >= Hc) hs -= Hc;
        int ws2 = wr + sw; if (ws2 >= Wc) ws2 -= Wc;
        const int tok = (b * Hc + hs) * Wc + ws2;
        tok_s[n] = tok;
        if (shifted) {
            int rh = (hr < Hc - wh) ? 0 : ((hr < Hc - sh) ? 1 : 2);
            int rw = (wr < Wc - ww) ? 0 : ((wr < Wc - sw) ? 1 : 2);
            rg_s[n] = rh * 3 + rw;
        }
        const float4* qp = (const float4*)g_qkv;
        const size_t base4 = (size_t)tok * 45 + (size_t)head * 5;
        const float scale = 0.223606797749979f;   // 20^-0.5
#pragma unroll
        for (int i = 0; i < 5; i++) {
            float4 q = qp[base4 + i];
            float4 k = qp[base4 + 15 + i];
            float4 v = qp[base4 + 30 + i];
            uint4 qo, ko, vo;
            qo.x = f2tf(q.x * scale); qo.y = f2tf(q.y * scale);
            qo.z = f2tf(q.z * scale); qo.w = f2tf(q.w * scale);
            ko.x = f2tf(k.x); ko.y = f2tf(k.y); ko.z = f2tf(k.z); ko.w = f2tf(k.w);
            vo.x = f2tf(v.x); vo.y = f2tf(v.y); vo.z = f2tf(v.z); vo.w = f2tf(v.w);
            p_s[n * KST + 4 * i + 0] = __uint_as_float(qo.x);
            p_s[n * KST + 4 * i + 1] = __uint_as_float(qo.y);
            p_s[n * KST + 4 * i + 2] = __uint_as_float(qo.z);
            p_s[n * KST + 4 * i + 3] = __uint_as_float(qo.w);
            k_s[n * KST + 4 * i + 0] = __uint_as_float(ko.x);
            k_s[n * KST + 4 * i + 1] = __uint_as_float(ko.y);
            k_s[n * KST + 4 * i + 2] = __uint_as_float(ko.z);
            k_s[n * KST + 4 * i + 3] = __uint_as_float(ko.w);
            v_s[n * VST + 4 * i + 0] = __uint_as_float(vo.x);
            v_s[n * VST + 4 * i + 1] = __uint_as_float(vo.y);
            v_s[n * VST + 4 * i + 2] = __uint_as_float(vo.z);
            v_s[n * VST + 4 * i + 3] = __uint_as_float(vo.w);
        }
#pragma unroll
        for (int c = 20; c < 24; c++) {
            p_s[n * KST + c] = 0.f;
            k_s[n * KST + c] = 0.f;
            v_s[n * VST + c] = 0.f;
        }
    }
    __syncthreads();

    const int wr0 = wid * 32;
    uint32_t qf[2][3][4];
    int rgA[2], rgB[2];
#pragma unroll
    for (int mt = 0; mt < 2; mt++) {
        const int r0 = wr0 + mt * 16 + g;
#pragma unroll
        for (int kt = 0; kt < 3; kt++) {
            const int c = kt * 8 + tg;
            qf[mt][kt][0] = __float_as_uint(p_s[r0 * KST + c]);
            qf[mt][kt][1] = __float_as_uint(p_s[(r0 + 8) * KST + c]);
            qf[mt][kt][2] = __float_as_uint(p_s[r0 * KST + c + 4]);
            qf[mt][kt][3] = __float_as_uint(p_s[(r0 + 8) * KST + c + 4]);
        }
        if (shifted) { rgA[mt] = rg_s[r0]; rgB[mt] = rg_s[r0 + 8]; }
    }
    __syncthreads();

    float oacc[2][3][4];
#pragma unroll
    for (int mt = 0; mt < 2; mt++)
#pragma unroll
        for (int nt = 0; nt < 3; nt++)
#pragma unroll
            for (int j = 0; j < 4; j++) oacc[mt][nt][j] = 0.f;
    float dsum[2][2] = {{0.f, 0.f}, {0.f, 0.f}};

    for (int c = 0; c < 8; c++) {
        const int kb = c * 32;
#pragma unroll
        for (int mt = 0; mt < 2; mt++) {
            float sacc[4][4];
#pragma unroll
            for (int nt = 0; nt < 4; nt++)
#pragma unroll
                for (int j = 0; j < 4; j++) sacc[nt][j] = 0.f;
#pragma unroll
            for (int kt = 0; kt < 3; kt++) {
                const int k0 = kt * 8;
#pragma unroll
                for (int nt = 0; nt < 4; nt++) {
                    const int nb = kb + nt * 8 + g;
                    uint32_t b0 = __float_as_uint(k_s[nb * KST + k0 + tg]);
                    uint32_t b1 = __float_as_uint(k_s[nb * KST + k0 + tg + 4]);
                    mma_tf32(sacc[nt], qf[mt][kt][0], qf[mt][kt][1],
                             qf[mt][kt][2], qf[mt][kt][3], b0, b1);
                }
            }
            const int r0 = wr0 + mt * 16 + g;
#pragma unroll
            for (int nt = 0; nt < 4; nt++) {
                const int col0 = kb + nt * 8 + 2 * tg;
                float s0 = sacc[nt][0], s1 = sacc[nt][1];
                float s2 = sacc[nt][2], s3 = sacc[nt][3];
                if (shifted) {
                    int rc0 = rg_s[col0], rc1 = rg_s[col0 + 1];
                    if (rc0 != rgA[mt]) s0 -= 100.f;
                    if (rc1 != rgA[mt]) s1 -= 100.f;
                    if (rc0 != rgB[mt]) s2 -= 100.f;
                    if (rc1 != rgB[mt]) s3 -= 100.f;
                }
                float p0 = __expf(s0), p1 = __expf(s1);
                float p2 = __expf(s2), p3 = __expf(s3);
                dsum[mt][0] += p0 + p1;
                dsum[mt][1] += p2 + p3;
                uint2 u0 = make_uint2(f2tf(p0), f2tf(p1));
                uint2 u1 = make_uint2(f2tf(p2), f2tf(p3));
                *(uint2*)(p_s + r0 * PST + nt * 8 + 2 * tg)       = u0;
                *(uint2*)(p_s + (r0 + 8) * PST + nt * 8 + 2 * tg) = u1;
            }
        }
        __syncwarp();
#pragma unroll
        for (int kt2 = 0; kt2 < 4; kt2++) {
            const int kr = kb + kt2 * 8;
#pragma unroll
            for (int mt = 0; mt < 2; mt++) {
                const int r0 = wr0 + mt * 16 + g;
                uint32_t a0 = __float_as_uint(p_s[r0 * PST + kt2 * 8 + tg]);
                uint32_t a1 = __float_as_uint(p_s[(r0 + 8) * PST + kt2 * 8 + tg]);
                uint32_t a2 = __float_as_uint(p_s[r0 * PST + kt2 * 8 + tg + 4]);
                uint32_t a3 = __float_as_uint(p_s[(r0 + 8) * PST + kt2 * 8 + tg + 4]);
#pragma unroll
                for (int nt = 0; nt < 3; nt++) {
                    const int nb = nt * 8 + g;
                    uint32_t b0 = __float_as_uint(v_s[(kr + tg) * VST + nb]);
                    uint32_t b1 = __float_as_uint(v_s[(kr + tg + 4) * VST + nb]);
                    mma_tf32(oacc[mt][nt], a0, a1, a2, a3, b0, b1);
                }
            }
        }
        __syncwarp();
    }

    float inv[2][2];
#pragma unroll
    for (int mt = 0; mt < 2; mt++)
#pragma unroll
        for (int j = 0; j < 2; j++) {
            float d = dsum[mt][j];
            d += __shfl_xor_sync(0xFFFFFFFFu, d, 1);
            d += __shfl_xor_sync(0xFFFFFFFFu, d, 2);
            inv[mt][j] = 1.f / d;
        }

#pragma unroll
    for (int mt = 0; mt < 2; mt++) {
        const int r0 = wr0 + mt * 16 + g;
        const int tok0 = tok_s[r0];
        const int tok1 = tok_s[r0 + 8];
#pragma unroll
        for (int nt = 0; nt < 3; nt++) {
            const int col = nt * 8 + 2 * tg;
            if (col < 20) {
                float2 w0 = make_float2(oacc[mt][nt][0] * inv[mt][0],
                                        oacc[mt][nt][1] * inv[mt][0]);
                float2 w1 = make_float2(oacc[mt][nt][2] * inv[mt][1],
                                        oacc[mt][nt][3] * inv[mt][1]);
                *(float2*)(g_attn + (size_t)tok0 * Cch + head * 20 + col) = w0;
                *(float2*)(g_attn + (size_t)tok1 * Cch + head * 20 + col) = w1;
            }
        }
    }
}

// ---------------------------------------------------------------------------
// conv3x3 60->12 + PixelShuffle(2) fused.
// ---------------------------------------------------------------------------
__global__ __launch_bounds__(256) void conv_out_k(
    const float* __restrict__ lw, const float* __restrict__ lb,
    float* __restrict__ out)
{
    const int TOT = Bn * 3 * 256 * 256;
    int idx = blockIdx.x * blockDim.x + threadIdx.x;
    if (idx >= TOT) return;
    int w2 = idx & 255;
    int h2 = (idx >> 8) & 255;
    int c  = (idx >> 16) % 3;
    int bb = idx / (3 * 65536);
    int co = c * 4 + (h2 & 1) * 2 + (w2 & 1);
    int h  = h2 >> 1, w = w2 >> 1;
    float acc = lb[co];
#pragma unroll
    for (int kh = 0; kh < 3; kh++) {
        int hh = h + kh - 1;
        if ((unsigned)hh >= (unsigned)Hc) continue;
#pragma unroll
        for (int kw = 0; kw < 3; kw++) {
            int ww2 = w + kw - 1;
            if ((unsigned)ww2 >= (unsigned)Wc) continue;
            const float* fp = g_feat + ((size_t)(bb * Hc + hh) * Wc + ww2) * Cch;
            const float* wp = lw + co * (Cch * 9) + kh * 3 + kw;
#pragma unroll
            for (int ci = 0; ci < Cch; ci++)
                acc = fmaf(fp[ci], wp[ci * 9], acc);
        }
    }
    out[idx] = acc;
}

// ---------------------------------------------------------------------------
// Launch
// ---------------------------------------------------------------------------
extern "C" void kernel_launch(void* const* d_in, const int* in_sizes, int n_in,
                              void* d_out, int out_size)
{
    (void)in_sizes; (void)n_in; (void)out_size;
    const float* x      = (const float*)d_in[0];
    const float* conv_w = (const float*)d_in[1];
    const float* conv_b = (const float*)d_in[2];
    const float* ln1_g  = (const float*)d_in[3];
    const float* ln1_b  = (const float*)d_in[4];
    const float* qkv_w  = (const float*)d_in[5];
    const float* qkv_b  = (const float*)d_in[6];
    const float* proj_w = (const float*)d_in[7];
    const float* proj_b = (const float*)d_in[8];
    const float* ln2_g  = (const float*)d_in[9];
    const float* ln2_b  = (const float*)d_in[10];
    const float* fc1_w  = (const float*)d_in[11];
    const float* fc1_b  = (const float*)d_in[12];
    const float* fc2_w  = (const float*)d_in[13];
    const float* fc2_b  = (const float*)d_in[14];
    const float* last_w = (const float*)d_in[15];
    const float* last_b = (const float*)d_in[16];
    float* out = (float*)d_out;

    constexpr int SM_QKV  = (64 * 200 + 192 + 120 + 128 + 64 * 68) * 4;  // 70368
    constexpr int SM_FPM  = 17464 * 4;                                   // 69856
    constexpr int SM_ATTN = (256 * 28 + 256 * 24 + 256 * 36 + 512) * 4;  // 92160

    cudaFuncSetAttribute(qkv_gemm_k<3>,
        cudaFuncAttributeMaxDynamicSharedMemorySize, SM_QKV);
    cudaFuncSetAttribute(fused_pm_k,
        cudaFuncAttributeMaxDynamicSharedMemorySize, SM_FPM);
    cudaFuncSetAttribute(attn_mma_k,
        cudaFuncAttributeMaxDynamicSharedMemorySize, SM_ATTN);

    // one-time weight prep
    prep_w_k<60, 180, 64, 200, 0><<<dim3(50, NL), 256>>>(qkv_w);
    prep_w_k<60, 60, 64, 72, 1><<<dim3(18, NL), 256>>>(proj_w);
    prep_w_k<60, 120, 64, 136, 2><<<dim3(34, NL), 256>>>(fc1_w);
    prep_w_k<120, 60, 120, 72, 3><<<dim3(34, NL), 256>>>(fc2_w);

    conv_in_k<<<(NTOK * Cch + 255) / 256, 256>>>(x, conv_w, conv_b);

    for (int l = 0; l < NL; l++) {
        int i  = l % 6;
        int wi = i % 2;
        int wh = wi ? 8 : 32;
        int ww = wi ? 32 : 8;
        int shifted = (i % 4) >= 2;
        int sh = shifted ? (wi ? 4 : 16) : 0;
        int sw = shifted ? (wi ? 16 : 4) : 0;

        qkv_gemm_k<3><<<NTOK / 64, 256, SM_QKV>>>(ln1_g + l * 60,
                                                  ln1_b + l * 60,
                                                  qkv_b + l * 180, l);

        attn_mma_k<<<dim3(Bn * 64, NHEADS), 256, SM_ATTN>>>(wh, ww, sh, sw,
                                                            shifted);

        fused_pm_k<<<NTOK / 32, 256, SM_FPM>>>(ln2_g + l * 60, ln2_b + l * 60,
                                               proj_b + l * 60,
                                               fc1_b + l * 120,
                                               fc2_b + l * 60, l);
    }

    conv_out_k<<<(Bn * 3 * 256 * 256 + 255) / 256, 256>>>(last_w, last_b, out);
}

// round 17
// speedup vs baseline: 2.1118x; 1.0799x over previous
#include <cuda_runtime.h>
#include <cstdint>

// ---------------------------------------------------------------------------
// SwinIR-lite forward.  B=2, H=W=128, C=60.
// R17: fused_pm reworked to TM=64 tokens/block, 512 thr, grid 512
//      (halves per-launch W-broadcast traffic 90->45MB; 32 warps/SM).
//      qkv/attn/convs unchanged from R16.
// ---------------------------------------------------------------------------

constexpr int Bn   = 2;
constexpr int Hc   = 128;
constexpr int Wc   = 128;
constexpr int Cch  = 60;
constexpr int NHEADS = 3;
constexpr int NTOK = Bn * Hc * Wc;          // 32768 tokens
constexpr int NL   = 36;

// Scratch (device globals; no allocation allowed)
__device__ float g_feat[NTOK * Cch];        // 7.5 MB
__device__ float g_qkv [NTOK * 180];        // 22.5 MB
__device__ float g_attn[NTOK * Cch];        // 7.5 MB

// Pre-converted tf32 weight slabs (padded to Kp x WST)
__device__ float g_wq[NL * 64 * 200];       // qkv  (K=60,N=180)
__device__ float g_wp[NL * 64 * 72];        // proj (K=60,N=60)
__device__ float g_w1[NL * 64 * 136];       // fc1  (K=60,N=120)
__device__ float g_w2[NL * 120 * 72];       // fc2  (K=120,N=60)

// ---- tf32 helpers ----------------------------------------------------------
__device__ __forceinline__ uint32_t f2tf(float v) {
    uint32_t r;
    asm("cvt.rna.tf32.f32 %0, %1;" : "=r"(r) : "f"(v));
    return r;
}
__device__ __forceinline__ void mma_tf32(float c[4],
    uint32_t a0, uint32_t a1, uint32_t a2, uint32_t a3,
    uint32_t b0, uint32_t b1)
{
    asm("mma.sync.aligned.m16n8k8.row.col.f32.tf32.tf32.f32 "
        "{%0,%1,%2,%3}, {%4,%5,%6,%7}, {%8,%9}, {%0,%1,%2,%3};"
        : "+f"(c[0]), "+f"(c[1]), "+f"(c[2]), "+f"(c[3])
        : "r"(a0), "r"(a1), "r"(a2), "r"(a3), "r"(b0), "r"(b1));
}

// ---------------------------------------------------------------------------
// Weight prep: convert + pad all layers of one family into tf32 slab.
// ---------------------------------------------------------------------------
template <int K, int N, int Kp, int WST, int FAM>
__global__ __launch_bounds__(256) void prep_w_k(const float* __restrict__ src)
{
    const int l = blockIdx.y;
    const int i = blockIdx.x * 256 + threadIdx.x;
    if (i >= Kp * WST) return;
    const int row = i / WST, col = i % WST;
    float v = 0.f;
    if (row < K && col < N) v = src[(size_t)l * K * N + row * N + col];
    float* dst = (FAM == 0) ? g_wq : (FAM == 1) ? g_wp
               : (FAM == 2) ? g_w1 : g_w2;
    dst[(size_t)l * (Kp * WST) + i] = __uint_as_float(f2tf(v));
}

// ---------------------------------------------------------------------------
// conv3x3 3->60, NCHW in -> NHWC (token-major) out
// ---------------------------------------------------------------------------
__global__ __launch_bounds__(256) void conv_in_k(
    const float* __restrict__ x, const float* __restrict__ w,
    const float* __restrict__ b)
{
    int idx = blockIdx.x * blockDim.x + threadIdx.x;
    if (idx >= NTOK * Cch) return;
    int co = idx % Cch;
    int p  = idx / Cch;
    int wx = p % Wc;
    int hy = (p / Wc) % Hc;
    int bb = p / (Wc * Hc);
    float acc = b[co];
#pragma unroll
    for (int ci = 0; ci < 3; ci++) {
#pragma unroll
        for (int kh = 0; kh < 3; kh++) {
            int hh = hy + kh - 1;
            if ((unsigned)hh >= (unsigned)Hc) continue;
#pragma unroll
            for (int kw = 0; kw < 3; kw++) {
                int ww2 = wx + kw - 1;
                if ((unsigned)ww2 >= (unsigned)Wc) continue;
                acc += x[((bb * 3 + ci) * Hc + hh) * Wc + ww2] *
                       w[((co * 3 + ci) * 3 + kh) * 3 + kw];
            }
        }
    }
    g_feat[idx] = acc;
}

// ---------------------------------------------------------------------------
// qkv GEMM (LN1 + X@Wq + bias -> g_qkv), unchanged from R16.
// TM=64 tokens, 256 thr, grid 512.
// ---------------------------------------------------------------------------
template <int MINB>
__global__ __launch_bounds__(256, MINB) void qkv_gemm_k(
    const float* __restrict__ gamma, const float* __restrict__ beta,
    const float* __restrict__ bias, int l)
{
    constexpr int K = 60, Kp = 64, XST = 68, N = 180, Np = 192, WST = 200;
    constexpr int NT = 12, KT = 8;
    extern __shared__ float sm[];
    float* ws   = sm;                    // Kp * WST
    float* bs   = ws + Kp * WST;         // Np
    float* gs   = bs + Np;               // K
    float* bt   = gs + K;                // K
    float* mu_s = bt + K;                // 64
    float* rs_s = mu_s + 64;             // 64
    float* xs   = rs_s + 64;             // 64 * XST

    const int tid = threadIdx.x;
    const int T0  = blockIdx.x * 64;

    {
        const uint4* s4 = (const uint4*)(g_wq + (size_t)l * (Kp * WST));
        uint4*       d4 = (uint4*)ws;
        for (int i = tid; i < Kp * WST / 4; i += 256) d4[i] = s4[i];
    }
    for (int i = tid; i < Np; i += 256) bs[i] = (i < N) ? bias[i] : 0.f;
    for (int i = tid; i < K; i += 256) { gs[i] = gamma[i]; bt[i] = beta[i]; }

    {
        constexpr int KP4 = Kp / 4;
        for (int i = tid; i < 64 * KP4; i += 256) {
            int row = i / KP4, c4 = (i % KP4) * 4;
            float4 v = make_float4(0.f, 0.f, 0.f, 0.f);
            if (c4 < K) v = *(const float4*)(g_feat + (size_t)(T0 + row) * K + c4);
            *(float4*)(xs + row * XST + c4) = v;
        }
    }
    __syncthreads();

    if (tid < 64) {
        float s = 0.f, s2 = 0.f;
        for (int k = 0; k < K; k++) {
            float v = xs[tid * XST + k];
            s += v; s2 += v * v;
        }
        float mu  = s * (1.0f / K);
        float var = s2 * (1.0f / K) - mu * mu;
        mu_s[tid] = mu;
        rs_s[tid] = rsqrtf(var + 1e-5f);
    }
    __syncthreads();
    for (int i = tid; i < 64 * K; i += 256) {
        int row = i / K, k = i % K;
        float v = xs[row * XST + k];
        v = (v - mu_s[row]) * rs_s[row] * gs[k] + bt[k];
        xs[row * XST + k] = __uint_as_float(f2tf(v));
    }
    __syncthreads();

    const int wid = tid >> 5, lane = tid & 31;
    const int mt = wid >> 1, ng = wid & 1;
    const int g  = lane >> 2, tg = lane & 3;
    const int r0 = mt * 16 + g;

    float acc[NT][4];
#pragma unroll
    for (int nt = 0; nt < NT; nt++)
#pragma unroll
        for (int j = 0; j < 4; j++) acc[nt][j] = 0.f;

#pragma unroll
    for (int kt = 0; kt < KT; kt++) {
        const int k0 = kt * 8;
        uint32_t a0 = __float_as_uint(xs[r0 * XST + k0 + tg]);
        uint32_t a1 = __float_as_uint(xs[(r0 + 8) * XST + k0 + tg]);
        uint32_t a2 = __float_as_uint(xs[r0 * XST + k0 + tg + 4]);
        uint32_t a3 = __float_as_uint(xs[(r0 + 8) * XST + k0 + tg + 4]);
#pragma unroll
        for (int nt = 0; nt < NT; nt++) {
            const int nb = (ng * NT + nt) * 8 + g;
            uint32_t b0 = __float_as_uint(ws[(k0 + tg) * WST + nb]);
            uint32_t b1 = __float_as_uint(ws[(k0 + tg + 4) * WST + nb]);
            mma_tf32(acc[nt], a0, a1, a2, a3, b0, b1);
        }
    }

    const int gr0 = T0 + mt * 16 + g;
    const int gr1 = gr0 + 8;
#pragma unroll
    for (int nt = 0; nt < NT; nt++) {
        const int col = (ng * NT + nt) * 8 + 2 * tg;
        if (col < N) {
            *(float2*)(g_qkv + (size_t)gr0 * N + col) =
                make_float2(acc[nt][0] + bs[col], acc[nt][1] + bs[col + 1]);
            *(float2*)(g_qkv + (size_t)gr1 * N + col) =
                make_float2(acc[nt][2] + bs[col], acc[nt][3] + bs[col + 1]);
        }
    }
}

// ---------------------------------------------------------------------------
// FUSED proj + residual + LN2 + fc1 + swish + fc2 + residual.
// R17: 64 tokens/block, 512 thr (16 warps = 4 mtiles x 4 nslabs), grid 512.
// smem: ws(8704 reused Wp->W1->W2) bp(64) b1(128) b2(64) gs(60) bt(60)
//       mu(64) rs(64) xs(64x68) fs(64x68 fp32) hs(64x124 tf32)
//       = 25848 floats = 103392 B -> 2 blocks/SM (32 warps/SM).
// ---------------------------------------------------------------------------
__global__ __launch_bounds__(512, 2) void fused_pm_k(
    const float* __restrict__ gamma, const float* __restrict__ beta,
    const float* __restrict__ proj_b, const float* __restrict__ fc1_b,
    const float* __restrict__ fc2_b, int l)
{
    extern __shared__ float sm[];
    float* ws = sm;                 // 8704
    float* bp = ws + 8704;          // 64
    float* b1 = bp + 64;            // 128
    float* b2 = b1 + 128;           // 64
    float* gs = b2 + 64;            // 60
    float* bt = gs + 60;            // 60
    float* mu_s = bt + 60;          // 64
    float* rs_s = mu_s + 64;        // 64
    float* xs = rs_s + 64;          // 64*68 = 4352
    float* fs = xs + 4352;          // 64*68 = 4352
    float* hs = fs + 4352;          // 64*124 = 7936

    const int tid = threadIdx.x;
    const int T0  = blockIdx.x * 64;
    const int wid = tid >> 5, lane = tid & 31;
    const int mt = wid >> 2, ng = wid & 3;      // 4 mtiles x 4 nslabs
    const int g  = lane >> 2, tg = lane & 3;
    const int r0 = mt * 16 + g;                 // row in tile (and +8)

    // ---- phase 1: stage Wp, biases, LN params, x (attn, tf32), feat tile ----
    {
        const uint4* s4 = (const uint4*)(g_wp + (size_t)l * 4608);
        uint4*       d4 = (uint4*)ws;
        for (int i = tid; i < 4608 / 4; i += 512) d4[i] = s4[i];
    }
    for (int i = tid; i < 64; i += 512)  bp[i] = (i < 60) ? proj_b[i] : 0.f;
    for (int i = tid; i < 128; i += 512) b1[i] = (i < 120) ? fc1_b[i] : 0.f;
    for (int i = tid; i < 64; i += 512)  b2[i] = (i < 60) ? fc2_b[i] : 0.f;
    for (int i = tid; i < 60; i += 512) { gs[i] = gamma[i]; bt[i] = beta[i]; }
    for (int i = tid; i < 64 * 16; i += 512) {          // xs: Kp/4 = 16
        int row = i >> 4, c4 = (i & 15) * 4;
        float4 v = make_float4(0.f, 0.f, 0.f, 0.f);
        if (c4 < 60) v = *(const float4*)(g_attn + (size_t)(T0 + row) * 60 + c4);
        uint4 o;
        o.x = f2tf(v.x); o.y = f2tf(v.y); o.z = f2tf(v.z); o.w = f2tf(v.w);
        *(uint4*)(xs + row * 68 + c4) = o;
    }
    for (int i = tid; i < 64 * 17; i += 512) {          // fs: 68/4 = 17
        int row = i / 17, c4 = (i % 17) * 4;
        float4 v = make_float4(0.f, 0.f, 0.f, 0.f);
        if (c4 < 60) v = *(const float4*)(g_feat + (size_t)(T0 + row) * 60 + c4);
        *(float4*)(fs + row * 68 + c4) = v;
    }
    __syncthreads();

    // ---- proj mma (K=60/Kp=64, N=60/Np=64, NT=2 per nslab of 16 cols) ----
    {
        float acc[2][4];
#pragma unroll
        for (int nt = 0; nt < 2; nt++)
#pragma unroll
            for (int j = 0; j < 4; j++) acc[nt][j] = 0.f;
#pragma unroll
        for (int kt = 0; kt < 8; kt++) {
            const int k0 = kt * 8;
            uint32_t a0 = __float_as_uint(xs[r0 * 68 + k0 + tg]);
            uint32_t a1 = __float_as_uint(xs[(r0 + 8) * 68 + k0 + tg]);
            uint32_t a2 = __float_as_uint(xs[r0 * 68 + k0 + tg + 4]);
            uint32_t a3 = __float_as_uint(xs[(r0 + 8) * 68 + k0 + tg + 4]);
#pragma unroll
            for (int nt = 0; nt < 2; nt++) {
                const int nb = (ng * 2 + nt) * 8 + g;
                uint32_t b0 = __float_as_uint(ws[(k0 + tg) * 72 + nb]);
                uint32_t b1r = __float_as_uint(ws[(k0 + tg + 4) * 72 + nb]);
                mma_tf32(acc[nt], a0, a1, a2, a3, b0, b1r);
            }
        }
        // epilogue: + bias + residual(fs) -> fs (feat tile updated in smem)
#pragma unroll
        for (int nt = 0; nt < 2; nt++) {
            const int col = (ng * 2 + nt) * 8 + 2 * tg;
            if (col < 60) {
                float2 f0 = *(float2*)(fs + r0 * 68 + col);
                float2 f1 = *(float2*)(fs + (r0 + 8) * 68 + col);
                f0.x += acc[nt][0] + bp[col];
                f0.y += acc[nt][1] + bp[col + 1];
                f1.x += acc[nt][2] + bp[col];
                f1.y += acc[nt][3] + bp[col + 1];
                *(float2*)(fs + r0 * 68 + col) = f0;
                *(float2*)(fs + (r0 + 8) * 68 + col) = f1;
            }
        }
    }
    __syncthreads();

    // ---- stage W1 (overwrites Wp) + LN2 stats ----
    {
        const uint4* s4 = (const uint4*)(g_w1 + (size_t)l * 8704);
        uint4*       d4 = (uint4*)ws;
        for (int i = tid; i < 8704 / 4; i += 512) d4[i] = s4[i];
    }
    if (tid < 64) {
        float s = 0.f, s2 = 0.f;
        for (int k = 0; k < 60; k++) {
            float v = fs[tid * 68 + k];
            s += v; s2 += v * v;
        }
        float mu  = s * (1.0f / 60.f);
        float var = s2 * (1.0f / 60.f) - mu * mu;
        mu_s[tid] = mu;
        rs_s[tid] = rsqrtf(var + 1e-5f);
    }
    __syncthreads();

    // ---- normalize into xs (tf32); cols 60..63 already zero ----
    for (int i = tid; i < 64 * 60; i += 512) {
        int row = i / 60, k = i % 60;
        float v = (fs[row * 68 + k] - mu_s[row]) * rs_s[row] * gs[k] + bt[k];
        xs[row * 68 + k] = __uint_as_float(f2tf(v));
    }
    __syncthreads();

    // ---- fc1 mma (K=60/Kp=64, N=120/Np=128, NT=4 per nslab of 32) + swish ----
    {
        float acc[4][4];
#pragma unroll
        for (int nt = 0; nt < 4; nt++)
#pragma unroll
            for (int j = 0; j < 4; j++) acc[nt][j] = 0.f;
#pragma unroll
        for (int kt = 0; kt < 8; kt++) {
            const int k0 = kt * 8;
            uint32_t a0 = __float_as_uint(xs[r0 * 68 + k0 + tg]);
            uint32_t a1 = __float_as_uint(xs[(r0 + 8) * 68 + k0 + tg]);
            uint32_t a2 = __float_as_uint(xs[r0 * 68 + k0 + tg + 4]);
            uint32_t a3 = __float_as_uint(xs[(r0 + 8) * 68 + k0 + tg + 4]);
#pragma unroll
            for (int nt = 0; nt < 4; nt++) {
                const int nb = (ng * 4 + nt) * 8 + g;
                uint32_t b0 = __float_as_uint(ws[(k0 + tg) * 136 + nb]);
                uint32_t b1r = __float_as_uint(ws[(k0 + tg + 4) * 136 + nb]);
                mma_tf32(acc[nt], a0, a1, a2, a3, b0, b1r);
            }
        }
#pragma unroll
        for (int nt = 0; nt < 4; nt++) {
            const int col = (ng * 4 + nt) * 8 + 2 * tg;
            if (col < 120) {
                float v0 = acc[nt][0] + b1[col];
                float v1 = acc[nt][1] + b1[col + 1];
                float v2 = acc[nt][2] + b1[col];
                float v3 = acc[nt][3] + b1[col + 1];
                v0 /= 1.f + __expf(-v0);  v1 /= 1.f + __expf(-v1);
                v2 /= 1.f + __expf(-v2);  v3 /= 1.f + __expf(-v3);
                *(uint2*)(hs + r0 * 124 + col) =
                    make_uint2(f2tf(v0), f2tf(v1));
                *(uint2*)(hs + (r0 + 8) * 124 + col) =
                    make_uint2(f2tf(v2), f2tf(v3));
            }
        }
    }
    __syncthreads();

    // ---- stage W2 (overwrites W1) ----
    {
        const uint4* s4 = (const uint4*)(g_w2 + (size_t)l * 8640);
        uint4*       d4 = (uint4*)ws;
        for (int i = tid; i < 8640 / 4; i += 512) d4[i] = s4[i];
    }
    __syncthreads();

    // ---- fc2 mma (K=120, N=60/Np=64, NT=2) + residual(fs) -> g_feat ----
    {
        float acc[2][4];
#pragma unroll
        for (int nt = 0; nt < 2; nt++)
#pragma unroll
            for (int j = 0; j < 4; j++) acc[nt][j] = 0.f;
#pragma unroll
        for (int kt = 0; kt < 15; kt++) {
            const int k0 = kt * 8;
            uint32_t a0 = __float_as_uint(hs[r0 * 124 + k0 + tg]);
            uint32_t a1 = __float_as_uint(hs[(r0 + 8) * 124 + k0 + tg]);
            uint32_t a2 = __float_as_uint(hs[r0 * 124 + k0 + tg + 4]);
            uint32_t a3 = __float_as_uint(hs[(r0 + 8) * 124 + k0 + tg + 4]);
#pragma unroll
            for (int nt = 0; nt < 2; nt++) {
                const int nb = (ng * 2 + nt) * 8 + g;
                uint32_t b0 = __float_as_uint(ws[(k0 + tg) * 72 + nb]);
                uint32_t b1r = __float_as_uint(ws[(k0 + tg + 4) * 72 + nb]);
                mma_tf32(acc[nt], a0, a1, a2, a3, b0, b1r);
            }
        }
        const int gr0 = T0 + r0;
        const int gr1 = gr0 + 8;
#pragma unroll
        for (int nt = 0; nt < 2; nt++) {
            const int col = (ng * 2 + nt) * 8 + 2 * tg;
            if (col < 60) {
                float2 f0 = *(float2*)(fs + r0 * 68 + col);
                float2 f1 = *(float2*)(fs + (r0 + 8) * 68 + col);
                *(float2*)(g_feat + (size_t)gr0 * 60 + col) =
                    make_float2(f0.x + acc[nt][0] + b2[col],
                                f0.y + acc[nt][1] + b2[col + 1]);
                *(float2*)(g_feat + (size_t)gr1 * 60 + col) =
                    make_float2(f1.x + acc[nt][2] + b2[col],
                                f1.y + acc[nt][3] + b2[col + 1]);
            }
        }
    }
}

// ---------------------------------------------------------------------------
// Tensor-core window attention (unchanged from R12).
// ---------------------------------------------------------------------------
__global__ __launch_bounds__(256, 2) void attn_mma_k(int wh, int ww,
                                                     int sh, int sw,
                                                     int shifted)
{
    constexpr int KST = 28, VST = 24, PST = 36;
    extern __shared__ float asm_[];
    float* k_s   = asm_;                    // 256*28
    float* v_s   = k_s + 256 * KST;         // 256*24
    float* p_s   = v_s + 256 * VST;         // 256*36 (Q staging first)
    int*   tok_s = (int*)(p_s + 256 * PST); // 256
    int*   rg_s  = tok_s + 256;             // 256

    const int tid  = threadIdx.x;
    const int wid  = tid >> 5, lane = tid & 31;
    const int g    = lane >> 2, tg = lane & 3;
    const int head = blockIdx.y;
    const int win  = blockIdx.x;
    const int nW   = Wc / ww;
    const int perB = (Hc / wh) * nW;
    const int b    = win / perB;
    const int wr_  = win % perB;
    const int wy   = wr_ / nW, wx = wr_ % nW;

    {
        const int n  = tid;
        const int iy = n / ww, ix = n % ww;
        const int hr = wy * wh + iy;
        const int wr = wx * ww + ix;
        int hs = hr + sh;  if (hs >= Hc) hs -= Hc;
        int ws2 = wr + sw; if (ws2 >= Wc) ws2 -= Wc;
        const int tok = (b * Hc + hs) * Wc + ws2;
        tok_s[n] = tok;
        if (shifted) {
            int rh = (hr < Hc - wh) ? 0 : ((hr < Hc - sh) ? 1 : 2);
            int rw = (wr < Wc - ww) ? 0 : ((wr < Wc - sw) ? 1 : 2);
            rg_s[n] = rh * 3 + rw;
        }
        const float4* qp = (const float4*)g_qkv;
        const size_t base4 = (size_t)tok * 45 + (size_t)head * 5;
        const float scale = 0.223606797749979f;   // 20^-0.5
#pragma unroll
        for (int i = 0; i < 5; i++) {
            float4 q = qp[base4 + i];
            float4 k = qp[base4 + 15 + i];
            float4 v = qp[base4 + 30 + i];
            uint4 qo, ko, vo;
            qo.x = f2tf(q.x * scale); qo.y = f2tf(q.y * scale);
            qo.z = f2tf(q.z * scale); qo.w = f2tf(q.w * scale);
            ko.x = f2tf(k.x); ko.y = f2tf(k.y); ko.z = f2tf(k.z); ko.w = f2tf(k.w);
            vo.x = f2tf(v.x); vo.y = f2tf(v.y); vo.z = f2tf(v.z); vo.w = f2tf(v.w);
            p_s[n * KST + 4 * i + 0] = __uint_as_float(qo.x);
            p_s[n * KST + 4 * i + 1] = __uint_as_float(qo.y);
            p_s[n * KST + 4 * i + 2] = __uint_as_float(qo.z);
            p_s[n * KST + 4 * i + 3] = __uint_as_float(qo.w);
            k_s[n * KST + 4 * i + 0] = __uint_as_float(ko.x);
            k_s[n * KST + 4 * i + 1] = __uint_as_float(ko.y);
            k_s[n * KST + 4 * i + 2] = __uint_as_float(ko.z);
            k_s[n * KST + 4 * i + 3] = __uint_as_float(ko.w);
            v_s[n * VST + 4 * i + 0] = __uint_as_float(vo.x);
            v_s[n * VST + 4 * i + 1] = __uint_as_float(vo.y);
            v_s[n * VST + 4 * i + 2] = __uint_as_float(vo.z);
            v_s[n * VST + 4 * i + 3] = __uint_as_float(vo.w);
        }
#pragma unroll
        for (int c = 20; c < 24; c++) {
            p_s[n * KST + c] = 0.f;
            k_s[n * KST + c] = 0.f;
            v_s[n * VST + c] = 0.f;
        }
    }
    __syncthreads();

    const int wr0 = wid * 32;
    uint32_t qf[2][3][4];
    int rgA[2], rgB[2];
#pragma unroll
    for (int mt = 0; mt < 2; mt++) {
        const int r0 = wr0 + mt * 16 + g;
#pragma unroll
        for (int kt = 0; kt < 3; kt++) {
            const int c = kt * 8 + tg;
            qf[mt][kt][0] = __float_as_uint(p_s[r0 * KST + c]);
            qf[mt][kt][1] = __float_as_uint(p_s[(r0 + 8) * KST + c]);
            qf[mt][kt][2] = __float_as_uint(p_s[r0 * KST + c + 4]);
            qf[mt][kt][3] = __float_as_uint(p_s[(r0 + 8) * KST + c + 4]);
        }
        if (shifted) { rgA[mt] = rg_s[r0]; rgB[mt] = rg_s[r0 + 8]; }
    }
    __syncthreads();

    float oacc[2][3][4];
#pragma unroll
    for (int mt = 0; mt < 2; mt++)
#pragma unroll
        for (int nt = 0; nt < 3; nt++)
#pragma unroll
            for (int j = 0; j < 4; j++) oacc[mt][nt][j] = 0.f;
    float dsum[2][2] = {{0.f, 0.f}, {0.f, 0.f}};

    for (int c = 0; c < 8; c++) {
        const int kb = c * 32;
#pragma unroll
        for (int mt = 0; mt < 2; mt++) {
            float sacc[4][4];
#pragma unroll
            for (int nt = 0; nt < 4; nt++)
#pragma unroll
                for (int j = 0; j < 4; j++) sacc[nt][j] = 0.f;
#pragma unroll
            for (int kt = 0; kt < 3; kt++) {
                const int k0 = kt * 8;
#pragma unroll
                for (int nt = 0; nt < 4; nt++) {
                    const int nb = kb + nt * 8 + g;
                    uint32_t b0 = __float_as_uint(k_s[nb * KST + k0 + tg]);
                    uint32_t b1 = __float_as_uint(k_s[nb * KST + k0 + tg + 4]);
                    mma_tf32(sacc[nt], qf[mt][kt][0], qf[mt][kt][1],
                             qf[mt][kt][2], qf[mt][kt][3], b0, b1);
                }
            }
            const int r0 = wr0 + mt * 16 + g;
#pragma unroll
            for (int nt = 0; nt < 4; nt++) {
                const int col0 = kb + nt * 8 + 2 * tg;
                float s0 = sacc[nt][0], s1 = sacc[nt][1];
                float s2 = sacc[nt][2], s3 = sacc[nt][3];
                if (shifted) {
                    int rc0 = rg_s[col0], rc1 = rg_s[col0 + 1];
                    if (rc0 != rgA[mt]) s0 -= 100.f;
                    if (rc1 != rgA[mt]) s1 -= 100.f;
                    if (rc0 != rgB[mt]) s2 -= 100.f;
                    if (rc1 != rgB[mt]) s3 -= 100.f;
                }
                float p0 = __expf(s0), p1 = __expf(s1);
                float p2 = __expf(s2), p3 = __expf(s3);
                dsum[mt][0] += p0 + p1;
                dsum[mt][1] += p2 + p3;
                uint2 u0 = make_uint2(f2tf(p0), f2tf(p1));
                uint2 u1 = make_uint2(f2tf(p2), f2tf(p3));
                *(uint2*)(p_s + r0 * PST + nt * 8 + 2 * tg)       = u0;
                *(uint2*)(p_s + (r0 + 8) * PST + nt * 8 + 2 * tg) = u1;
            }
        }
        __syncwarp();
#pragma unroll
        for (int kt2 = 0; kt2 < 4; kt2++) {
            const int kr = kb + kt2 * 8;
#pragma unroll
            for (int mt = 0; mt < 2; mt++) {
                const int r0 = wr0 + mt * 16 + g;
                uint32_t a0 = __float_as_uint(p_s[r0 * PST + kt2 * 8 + tg]);
                uint32_t a1 = __float_as_uint(p_s[(r0 + 8) * PST + kt2 * 8 + tg]);
                uint32_t a2 = __float_as_uint(p_s[r0 * PST + kt2 * 8 + tg + 4]);
                uint32_t a3 = __float_as_uint(p_s[(r0 + 8) * PST + kt2 * 8 + tg + 4]);
#pragma unroll
                for (int nt = 0; nt < 3; nt++) {
                    const int nb = nt * 8 + g;
                    uint32_t b0 = __float_as_uint(v_s[(kr + tg) * VST + nb]);
                    uint32_t b1 = __float_as_uint(v_s[(kr + tg + 4) * VST + nb]);
                    mma_tf32(oacc[mt][nt], a0, a1, a2, a3, b0, b1);
                }
            }
        }
        __syncwarp();
    }

    float inv[2][2];
#pragma unroll
    for (int mt = 0; mt < 2; mt++)
#pragma unroll
        for (int j = 0; j < 2; j++) {
            float d = dsum[mt][j];
            d += __shfl_xor_sync(0xFFFFFFFFu, d, 1);
            d += __shfl_xor_sync(0xFFFFFFFFu, d, 2);
            inv[mt][j] = 1.f / d;
        }

#pragma unroll
    for (int mt = 0; mt < 2; mt++) {
        const int r0 = wr0 + mt * 16 + g;
        const int tok0 = tok_s[r0];
        const int tok1 = tok_s[r0 + 8];
#pragma unroll
        for (int nt = 0; nt < 3; nt++) {
            const int col = nt * 8 + 2 * tg;
            if (col < 20) {
                float2 w0 = make_float2(oacc[mt][nt][0] * inv[mt][0],
                                        oacc[mt][nt][1] * inv[mt][0]);
                float2 w1 = make_float2(oacc[mt][nt][2] * inv[mt][1],
                                        oacc[mt][nt][3] * inv[mt][1]);
                *(float2*)(g_attn + (size_t)tok0 * Cch + head * 20 + col) = w0;
                *(float2*)(g_attn + (size_t)tok1 * Cch + head * 20 + col) = w1;
            }
        }
    }
}

// ---------------------------------------------------------------------------
// conv3x3 60->12 + PixelShuffle(2) fused.
// ---------------------------------------------------------------------------
__global__ __launch_bounds__(256) void conv_out_k(
    const float* __restrict__ lw, const float* __restrict__ lb,
    float* __restrict__ out)
{
    const int TOT = Bn * 3 * 256 * 256;
    int idx = blockIdx.x * blockDim.x + threadIdx.x;
    if (idx >= TOT) return;
    int w2 = idx & 255;
    int h2 = (idx >> 8) & 255;
    int c  = (idx >> 16) % 3;
    int bb = idx / (3 * 65536);
    int co = c * 4 + (h2 & 1) * 2 + (w2 & 1);
    int h  = h2 >> 1, w = w2 >> 1;
    float acc = lb[co];
#pragma unroll
    for (int kh = 0; kh < 3; kh++) {
        int hh = h + kh - 1;
        if ((unsigned)hh >= (unsigned)Hc) continue;
#pragma unroll
        for (int kw = 0; kw < 3; kw++) {
            int ww2 = w + kw - 1;
            if ((unsigned)ww2 >= (unsigned)Wc) continue;
            const float* fp = g_feat + ((size_t)(bb * Hc + hh) * Wc + ww2) * Cch;
            const float* wp = lw + co * (Cch * 9) + kh * 3 + kw;
#pragma unroll
            for (int ci = 0; ci < Cch; ci++)
                acc = fmaf(fp[ci], wp[ci * 9], acc);
        }
    }
    out[idx] = acc;
}

// ---------------------------------------------------------------------------
// Launch
// ---------------------------------------------------------------------------
extern "C" void kernel_launch(void* const* d_in, const int* in_sizes, int n_in,
                              void* d_out, int out_size)
{
    (void)in_sizes; (void)n_in; (void)out_size;
    const float* x      = (const float*)d_in[0];
    const float* conv_w = (const float*)d_in[1];
    const float* conv_b = (const float*)d_in[2];
    const float* ln1_g  = (const float*)d_in[3];
    const float* ln1_b  = (const float*)d_in[4];
    const float* qkv_w  = (const float*)d_in[5];
    const float* qkv_b  = (const float*)d_in[6];
    const float* proj_w = (const float*)d_in[7];
    const float* proj_b = (const float*)d_in[8];
    const float* ln2_g  = (const float*)d_in[9];
    const float* ln2_b  = (const float*)d_in[10];
    const float* fc1_w  = (const float*)d_in[11];
    const float* fc1_b  = (const float*)d_in[12];
    const float* fc2_w  = (const float*)d_in[13];
    const float* fc2_b  = (const float*)d_in[14];
    const float* last_w = (const float*)d_in[15];
    const float* last_b = (const float*)d_in[16];
    float* out = (float*)d_out;

    constexpr int SM_QKV  = (64 * 200 + 192 + 120 + 128 + 64 * 68) * 4;  // 70368
    constexpr int SM_FPM  = 25848 * 4;                                   // 103392
    constexpr int SM_ATTN = (256 * 28 + 256 * 24 + 256 * 36 + 512) * 4;  // 92160

    cudaFuncSetAttribute(qkv_gemm_k<3>,
        cudaFuncAttributeMaxDynamicSharedMemorySize, SM_QKV);
    cudaFuncSetAttribute(fused_pm_k,
        cudaFuncAttributeMaxDynamicSharedMemorySize, SM_FPM);
    cudaFuncSetAttribute(attn_mma_k,
        cudaFuncAttributeMaxDynamicSharedMemorySize, SM_ATTN);

    // one-time weight prep
    prep_w_k<60, 180, 64, 200, 0><<<dim3(50, NL), 256>>>(qkv_w);
    prep_w_k<60, 60, 64, 72, 1><<<dim3(18, NL), 256>>>(proj_w);
    prep_w_k<60, 120, 64, 136, 2><<<dim3(34, NL), 256>>>(fc1_w);
    prep_w_k<120, 60, 120, 72, 3><<<dim3(34, NL), 256>>>(fc2_w);

    conv_in_k<<<(NTOK * Cch + 255) / 256, 256>>>(x, conv_w, conv_b);

    for (int l = 0; l < NL; l++) {
        int i  = l % 6;
        int wi = i % 2;
        int wh = wi ? 8 : 32;
        int ww = wi ? 32 : 8;
        int shifted = (i % 4) >= 2;
        int sh = shifted ? (wi ? 4 : 16) : 0;
        int sw = shifted ? (wi ? 16 : 4) : 0;

        qkv_gemm_k<3><<<NTOK / 64, 256, SM_QKV>>>(ln1_g + l * 60,
                                                  ln1_b + l * 60,
                                                  qkv_b + l * 180, l);

        attn_mma_k<<<dim3(Bn * 64, NHEADS), 256, SM_ATTN>>>(wh, ww, sh, sw,
                                                            shifted);

        fused_pm_k<<<NTOK / 64, 512, SM_FPM>>>(ln2_g + l * 60, ln2_b + l * 60,
                                               proj_b + l * 60,
                                               fc1_b + l * 120,
                                               fc2_b + l * 60, l);
    }

    conv_out_k<<<(Bn * 3 * 256 * 256 + 255) / 256, 256>>>(last_w, last_b, out);
}